// round 2
// baseline (speedup 1.0000x reference)
#include <cuda_runtime.h>
#include <cstdint>

#define B_SZ 2
#define N_SZ 2048
#define D_SZ 2048
#define H_SZ 16
#define HD_SZ 128
#define M_SZ (B_SZ * N_SZ)   // 4096

// Scratch (static device arrays; no allocation allowed)
__device__ float g_q[M_SZ * D_SZ];
__device__ float g_k[M_SZ * D_SZ];
__device__ float g_v[M_SZ * D_SZ];
__device__ float g_att[M_SZ * D_SZ];

// ---------------------------------------------------------------------------
// SGEMM: C[M, Nn] = A[M, K] @ W[Nn, K]^T   (all row-major, fp32)
// 128x128 tile, BK=8, 256 threads, 8x8 per thread.
// ---------------------------------------------------------------------------
__global__ __launch_bounds__(256) void sgemm_nt(
    const float* __restrict__ A, const float* __restrict__ W,
    float* __restrict__ C, int M, int Nn, int K) {
    __shared__ float As[8][128];
    __shared__ float Bs[8][128];

    const int tid = threadIdx.x;
    const int tx = tid & 15;        // 0..15
    const int ty = tid >> 4;        // 0..15
    const int rowBase = blockIdx.y * 128;
    const int colBase = blockIdx.x * 128;

    const int lr = tid >> 1;        // 0..127
    const int lk = (tid & 1) * 4;   // 0 or 4

    const float* Aptr = A + (size_t)(rowBase + lr) * K + lk;
    const float* Wptr = W + (size_t)(colBase + lr) * K + lk;

    float acc[8][8];
#pragma unroll
    for (int i = 0; i < 8; i++)
#pragma unroll
        for (int j = 0; j < 8; j++) acc[i][j] = 0.0f;

    for (int k0 = 0; k0 < K; k0 += 8) {
        float4 av = *(const float4*)(Aptr + k0);
        float4 wv = *(const float4*)(Wptr + k0);
        As[lk + 0][lr] = av.x; As[lk + 1][lr] = av.y;
        As[lk + 2][lr] = av.z; As[lk + 3][lr] = av.w;
        Bs[lk + 0][lr] = wv.x; Bs[lk + 1][lr] = wv.y;
        Bs[lk + 2][lr] = wv.z; Bs[lk + 3][lr] = wv.w;
        __syncthreads();

#pragma unroll
        for (int kk = 0; kk < 8; kk++) {
            float a[8], b[8];
            *(float4*)(a)     = *(const float4*)&As[kk][ty * 8];
            *(float4*)(a + 4) = *(const float4*)&As[kk][ty * 8 + 4];
            *(float4*)(b)     = *(const float4*)&Bs[kk][tx * 8];
            *(float4*)(b + 4) = *(const float4*)&Bs[kk][tx * 8 + 4];
#pragma unroll
            for (int i = 0; i < 8; i++)
#pragma unroll
                for (int j = 0; j < 8; j++)
                    acc[i][j] += a[i] * b[j];
        }
        __syncthreads();
    }

#pragma unroll
    for (int i = 0; i < 8; i++) {
        float* cp = C + (size_t)(rowBase + ty * 8 + i) * Nn + colBase + tx * 8;
        float4 c0 = make_float4(acc[i][0], acc[i][1], acc[i][2], acc[i][3]);
        float4 c1 = make_float4(acc[i][4], acc[i][5], acc[i][6], acc[i][7]);
        *(float4*)(cp)     = c0;
        *(float4*)(cp + 4) = c1;
    }
}

// ---------------------------------------------------------------------------
// RoPE (in-place on g_q, g_k). Llama-style: pairs (i, i+64) within each head.
// ---------------------------------------------------------------------------
__global__ __launch_bounds__(256) void rope_kernel(float* __restrict__ q,
                                                   float* __restrict__ k) {
    int idx = blockIdx.x * blockDim.x + threadIdx.x;
    const int total = M_SZ * H_SZ * (HD_SZ / 2);
    if (idx >= total) return;

    int i = idx & 63;               // 0..63  (half-dim index)
    int h = (idx >> 6) & 15;        // head
    int m = idx >> 10;              // token row 0..4095
    int pos = m & (N_SZ - 1);       // n within sequence

    // inv_freq = 10000^(-i/64), computed in fp32 like the reference
    float inv_freq = powf(10000.0f, -(float)i * (1.0f / 64.0f));
    float f = (float)pos * inv_freq;
    float s, c;
    sincosf(f, &s, &c);

    size_t base = (size_t)m * D_SZ + h * HD_SZ;
    float q1 = q[base + i], q2 = q[base + 64 + i];
    q[base + i]      = q1 * c - q2 * s;
    q[base + 64 + i] = q2 * c + q1 * s;

    float k1 = k[base + i], k2 = k[base + 64 + i];
    k[base + i]      = k1 * c - k2 * s;
    k[base + 64 + i] = k2 * c + k1 * s;
}

// ---------------------------------------------------------------------------
// Flash attention, fp32. Block = 256 threads (8 warps), each warp owns 4
// query rows; key tiles of 32 (one key per lane). Online softmax in-warp.
// Layouts: q/k/v are [M, D] with head h at column h*128; output same.
// ---------------------------------------------------------------------------
#define AT_ROWS 32
#define KT 32
#define PAD 132   // row stride in floats; 132*4=528 B, 16B aligned, conflict-free

__global__ __launch_bounds__(256) void attn_kernel(
    const float* __restrict__ q, const float* __restrict__ k,
    const float* __restrict__ v, float* __restrict__ o) {
    __shared__ float qs[AT_ROWS][PAD];
    __shared__ float ks[KT][PAD];
    __shared__ float vs[KT][PAD];

    const int bh = blockIdx.y;           // 0..31
    const int b = bh >> 4, h = bh & 15;
    const int row0 = blockIdx.x * AT_ROWS;
    const int tid = threadIdx.x;
    const int warp = tid >> 5, lane = tid & 31;

    // Load Q tile: 32 rows x 128 floats = 1024 float4, 4 per thread
    const float* qbase = q + (size_t)(b * N_SZ + row0) * D_SZ + h * HD_SZ;
#pragma unroll
    for (int it = 0; it < 4; it++) {
        int e = tid + it * 256;
        int r = e >> 5, d4 = e & 31;
        float4 val = *(const float4*)(qbase + (size_t)r * D_SZ + d4 * 4);
        *(float4*)&qs[r][d4 * 4] = val;
    }

    float m_run[4], l_run[4], oacc[4][4];
#pragma unroll
    for (int rr = 0; rr < 4; rr++) {
        m_run[rr] = -1e30f;
        l_run[rr] = 0.0f;
#pragma unroll
        for (int d = 0; d < 4; d++) oacc[rr][d] = 0.0f;
    }

    const float scale = 0.08838834764831845f;  // 1/sqrt(128)
    const int myrow = warp * 4;

    for (int t = 0; t < N_SZ / KT; t++) {
        __syncthreads();
        // Load K/V tiles (32 rows x 128 floats each)
        const float* kbase = k + (size_t)(b * N_SZ + t * KT) * D_SZ + h * HD_SZ;
        const float* vbase = v + (size_t)(b * N_SZ + t * KT) * D_SZ + h * HD_SZ;
#pragma unroll
        for (int it = 0; it < 4; it++) {
            int e = tid + it * 256;
            int r = e >> 5, d4 = e & 31;
            *(float4*)&ks[r][d4 * 4] =
                *(const float4*)(kbase + (size_t)r * D_SZ + d4 * 4);
            *(float4*)&vs[r][d4 * 4] =
                *(const float4*)(vbase + (size_t)r * D_SZ + d4 * 4);
        }
        __syncthreads();

        // S = Q K^T : lane = key index within tile
        float s[4] = {0.f, 0.f, 0.f, 0.f};
#pragma unroll
        for (int d4 = 0; d4 < 32; d4++) {
            float4 kf = *(const float4*)&ks[lane][d4 * 4];
#pragma unroll
            for (int rr = 0; rr < 4; rr++) {
                float4 qf = *(const float4*)&qs[myrow + rr][d4 * 4];
                s[rr] += qf.x * kf.x + qf.y * kf.y + qf.z * kf.z + qf.w * kf.w;
            }
        }

        // Online softmax per row
#pragma unroll
        for (int rr = 0; rr < 4; rr++) {
            float sv = s[rr] * scale;
            float mt = sv;
#pragma unroll
            for (int off = 16; off > 0; off >>= 1)
                mt = fmaxf(mt, __shfl_xor_sync(0xFFFFFFFFu, mt, off));
            float mnew = fmaxf(m_run[rr], mt);
            float corr = __expf(m_run[rr] - mnew);
            float p = __expf(sv - mnew);
            float psum = p;
#pragma unroll
            for (int off = 16; off > 0; off >>= 1)
                psum += __shfl_xor_sync(0xFFFFFFFFu, psum, off);
            l_run[rr] = l_run[rr] * corr + psum;
            m_run[rr] = mnew;
#pragma unroll
            for (int d = 0; d < 4; d++) oacc[rr][d] *= corr;
            s[rr] = p;   // keep probability for PV
        }

        // O += P V : lane owns output dims [lane*4, lane*4+4)
#pragma unroll
        for (int j = 0; j < 32; j++) {
            float4 vf = *(const float4*)&vs[j][lane * 4];
#pragma unroll
            for (int rr = 0; rr < 4; rr++) {
                float pj = __shfl_sync(0xFFFFFFFFu, s[rr], j);
                oacc[rr][0] += pj * vf.x;
                oacc[rr][1] += pj * vf.y;
                oacc[rr][2] += pj * vf.z;
                oacc[rr][3] += pj * vf.w;
            }
        }
    }

    // Normalize and write out: [m][h*128 + lane*4]
#pragma unroll
    for (int rr = 0; rr < 4; rr++) {
        float inv = 1.0f / l_run[rr];
        int m = b * N_SZ + row0 + myrow + rr;
        float4 ov = make_float4(oacc[rr][0] * inv, oacc[rr][1] * inv,
                                oacc[rr][2] * inv, oacc[rr][3] * inv);
        *(float4*)(o + (size_t)m * D_SZ + h * HD_SZ + lane * 4) = ov;
    }
}

// ---------------------------------------------------------------------------
// Launch
// ---------------------------------------------------------------------------
extern "C" void kernel_launch(void* const* d_in, const int* in_sizes, int n_in,
                              void* d_out, int out_size) {
    const float* x  = (const float*)d_in[0];
    const float* Wq = (const float*)d_in[1];
    const float* Wk = (const float*)d_in[2];
    const float* Wv = (const float*)d_in[3];
    const float* Wo = (const float*)d_in[4];
    float* out = (float*)d_out;

    float *q_ptr, *k_ptr, *v_ptr, *att_ptr;
    cudaGetSymbolAddress((void**)&q_ptr, g_q);
    cudaGetSymbolAddress((void**)&k_ptr, g_k);
    cudaGetSymbolAddress((void**)&v_ptr, g_v);
    cudaGetSymbolAddress((void**)&att_ptr, g_att);

    dim3 gg(D_SZ / 128, M_SZ / 128);   // (16, 32)
    sgemm_nt<<<gg, 256>>>(x, Wq, q_ptr, M_SZ, D_SZ, D_SZ);
    sgemm_nt<<<gg, 256>>>(x, Wk, k_ptr, M_SZ, D_SZ, D_SZ);
    sgemm_nt<<<gg, 256>>>(x, Wv, v_ptr, M_SZ, D_SZ, D_SZ);

    int rope_total = M_SZ * H_SZ * (HD_SZ / 2);
    rope_kernel<<<(rope_total + 255) / 256, 256>>>(q_ptr, k_ptr);

    dim3 ga(N_SZ / AT_ROWS, B_SZ * H_SZ);  // (64, 32)
    attn_kernel<<<ga, 256>>>(q_ptr, k_ptr, v_ptr, att_ptr);

    sgemm_nt<<<gg, 256>>>(att_ptr, Wo, out, M_SZ, D_SZ, D_SZ);
}

// round 5
// speedup vs baseline: 1.4998x; 1.4998x over previous
#include <cuda_runtime.h>
#include <cuda_bf16.h>
#include <cstdint>

#define B_SZ 2
#define N_SZ 2048
#define D_SZ 2048
#define H_SZ 16
#define HD_SZ 128
#define M_SZ (B_SZ * N_SZ)   // 4096

// Scratch (static device arrays; no allocation allowed)
__device__ float g_q[M_SZ * D_SZ];
__device__ float g_k[M_SZ * D_SZ];
__device__ float g_v[M_SZ * D_SZ];
__device__ float g_att[M_SZ * D_SZ];

// ===========================================================================
// Warp-level MMA helpers (sm_80-era PTX: works at compute_103, no 'a' needed)
// ===========================================================================
__device__ __forceinline__ uint32_t smem_u32(const void* p) {
    uint32_t a;
    asm("{ .reg .u64 t; cvta.to.shared.u64 t, %1; cvt.u32.u64 %0, t; }"
        : "=r"(a) : "l"(p));
    return a;
}

__device__ __forceinline__ void ldsm_x4(uint32_t& r0, uint32_t& r1,
                                        uint32_t& r2, uint32_t& r3,
                                        uint32_t addr) {
    asm volatile("ldmatrix.sync.aligned.m8n8.x4.shared.b16 {%0,%1,%2,%3}, [%4];"
                 : "=r"(r0), "=r"(r1), "=r"(r2), "=r"(r3) : "r"(addr));
}

__device__ __forceinline__ void mma_bf16(float* d, const uint32_t* a,
                                         uint32_t b0, uint32_t b1) {
    asm volatile(
        "mma.sync.aligned.m16n8k16.row.col.f32.bf16.bf16.f32 "
        "{%0,%1,%2,%3}, {%4,%5,%6,%7}, {%8,%9}, {%0,%1,%2,%3};"
        : "+f"(d[0]), "+f"(d[1]), "+f"(d[2]), "+f"(d[3])
        : "r"(a[0]), "r"(a[1]), "r"(a[2]), "r"(a[3]), "r"(b0), "r"(b1));
}

// Split fp32x4 -> hi/lo bf16x2 pairs
__device__ __forceinline__ void split4(float4 f, uint2& hi, uint2& lo) {
    __nv_bfloat16 h0 = __float2bfloat16(f.x);
    __nv_bfloat16 h1 = __float2bfloat16(f.y);
    __nv_bfloat16 h2 = __float2bfloat16(f.z);
    __nv_bfloat16 h3 = __float2bfloat16(f.w);
    __nv_bfloat16 l0 = __float2bfloat16(f.x - __bfloat162float(h0));
    __nv_bfloat16 l1 = __float2bfloat16(f.y - __bfloat162float(h1));
    __nv_bfloat16 l2 = __float2bfloat16(f.z - __bfloat162float(h2));
    __nv_bfloat16 l3 = __float2bfloat16(f.w - __bfloat162float(h3));
    hi.x = (uint32_t)__bfloat16_as_ushort(h0) | ((uint32_t)__bfloat16_as_ushort(h1) << 16);
    hi.y = (uint32_t)__bfloat16_as_ushort(h2) | ((uint32_t)__bfloat16_as_ushort(h3) << 16);
    lo.x = (uint32_t)__bfloat16_as_ushort(l0) | ((uint32_t)__bfloat16_as_ushort(l1) << 16);
    lo.y = (uint32_t)__bfloat16_as_ushort(l2) | ((uint32_t)__bfloat16_as_ushort(l3) << 16);
}

// ===========================================================================
// HMMA GEMM: C[M, Nn] = A[M, K] @ W[Nn, K]^T  (fp32 in/out, 3x-bf16 split)
// CTA tile 128x128, BK=32, 256 threads, 8 warps (2m x 4n), warp tile 64x32.
// SMEM row stride 80 B (stride-5 bank groups, gcd(5,8)=1 -> conflict-free
// ldmatrix without XOR swizzle).
// ===========================================================================
#define BKF 32            // k elements per smem tile
#define RSB 40            // bf16 elements per smem row (80 bytes)

__global__ __launch_bounds__(256) void gemm_hmma(
    const float* __restrict__ A, const float* __restrict__ W,
    float* __restrict__ C, int K, int Nn) {
    __shared__ __align__(16) uint16_t sAh[128 * RSB];
    __shared__ __align__(16) uint16_t sAl[128 * RSB];
    __shared__ __align__(16) uint16_t sBh[128 * RSB];
    __shared__ __align__(16) uint16_t sBl[128 * RSB];

    const int tid = threadIdx.x;
    const int warp = tid >> 5;
    const int lane = tid & 31;
    const int wm = warp >> 2;         // 0..1
    const int wn = warp & 3;          // 0..3
    const int mbase = wm * 64;
    const int nbase = wn * 32;

    const uint32_t uAh = smem_u32(sAh);
    const uint32_t uAl = smem_u32(sAl);
    const uint32_t uBh = smem_u32(sBh);
    const uint32_t uBl = smem_u32(sBl);

    // Global load mapping: idx = tid + it*256 ; row = idx>>3, c4 = idx&7
    const int lrow = tid >> 3;        // base row (advances by 32 per it)
    const int lc4 = tid & 7;          // float4 column within 32-float row
    const float* Abase = A + (size_t)(blockIdx.y * 128) * K;
    const float* Wbase = W + (size_t)(blockIdx.x * 128) * K;

    float acc[4][4][4];
#pragma unroll
    for (int i = 0; i < 4; i++)
#pragma unroll
        for (int j = 0; j < 4; j++)
#pragma unroll
            for (int e = 0; e < 4; e++) acc[i][j][e] = 0.0f;

    const int niter = K / BKF;        // 64
    float4 pa[4], pb[4];

    // Prefetch tile 0
#pragma unroll
    for (int it = 0; it < 4; it++) {
        int r = lrow + it * 32;
        pa[it] = *(const float4*)(Abase + (size_t)r * K + lc4 * 4);
        pb[it] = *(const float4*)(Wbase + (size_t)r * K + lc4 * 4);
    }

    for (int kc = 0; kc < niter; kc++) {
        // Store current tile (split to hi/lo bf16) into smem
#pragma unroll
        for (int it = 0; it < 4; it++) {
            int r = lrow + it * 32;
            uint32_t off = (uint32_t)(r * 80 + lc4 * 8);
            uint2 hi, lo;
            split4(pa[it], hi, lo);
            *(uint2*)((char*)sAh + off) = hi;
            *(uint2*)((char*)sAl + off) = lo;
            split4(pb[it], hi, lo);
            *(uint2*)((char*)sBh + off) = hi;
            *(uint2*)((char*)sBl + off) = lo;
        }
        __syncthreads();

        // Prefetch next tile while MMAs run
        if (kc + 1 < niter) {
            const float* An = Abase + (kc + 1) * BKF;
            const float* Wn = Wbase + (kc + 1) * BKF;
#pragma unroll
            for (int it = 0; it < 4; it++) {
                int r = lrow + it * 32;
                pa[it] = *(const float4*)(An + (size_t)r * K + lc4 * 4);
                pb[it] = *(const float4*)(Wn + (size_t)r * K + lc4 * 4);
            }
        }

        const int g = lane >> 3, lr = lane & 7;
#pragma unroll
        for (int s = 0; s < 2; s++) {
            // A fragments: 4 m-tiles, hi and lo
            uint32_t ah[4][4], al[4][4];
            {
                uint32_t arow = (uint32_t)(mbase + lr + ((g & 1) << 3));
                uint32_t akb  = (uint32_t)(s * 32 + ((g >> 1) << 4));
                uint32_t aoff = arow * 80 + akb;
#pragma unroll
                for (int mi = 0; mi < 4; mi++) {
                    ldsm_x4(ah[mi][0], ah[mi][1], ah[mi][2], ah[mi][3],
                            uAh + aoff + mi * (16 * 80));
                    ldsm_x4(al[mi][0], al[mi][1], al[mi][2], al[mi][3],
                            uAl + aoff + mi * (16 * 80));
                }
            }
            // B fragments: 4 n-tiles via 2 x4-loads each array
            uint32_t bh[8], bl[8];
            {
                uint32_t brow = (uint32_t)(nbase + lr + ((g >> 1) << 3));
                uint32_t bkb  = (uint32_t)(s * 32 + ((g & 1) << 4));
                uint32_t boff = brow * 80 + bkb;
                ldsm_x4(bh[0], bh[1], bh[2], bh[3], uBh + boff);
                ldsm_x4(bh[4], bh[5], bh[6], bh[7], uBh + boff + 16 * 80);
                ldsm_x4(bl[0], bl[1], bl[2], bl[3], uBl + boff);
                ldsm_x4(bl[4], bl[5], bl[6], bl[7], uBl + boff + 16 * 80);
            }
#pragma unroll
            for (int mi = 0; mi < 4; mi++) {
#pragma unroll
                for (int ni = 0; ni < 4; ni++) {
                    mma_bf16(acc[mi][ni], ah[mi], bh[ni * 2], bh[ni * 2 + 1]);
                    mma_bf16(acc[mi][ni], ah[mi], bl[ni * 2], bl[ni * 2 + 1]);
                    mma_bf16(acc[mi][ni], al[mi], bh[ni * 2], bh[ni * 2 + 1]);
                }
            }
        }
        __syncthreads();
    }

    // Epilogue: frag (mi,ni): rows gid, gid+8 ; cols 2*tig + {0,1}
    const int gid = lane >> 2, tig = lane & 3;
    const int rowA = blockIdx.y * 128 + mbase + gid;
    const int colA = blockIdx.x * 128 + nbase + tig * 2;
#pragma unroll
    for (int mi = 0; mi < 4; mi++) {
#pragma unroll
        for (int ni = 0; ni < 4; ni++) {
            float* c0 = C + (size_t)(rowA + mi * 16) * Nn + colA + ni * 8;
            float* c1 = C + (size_t)(rowA + mi * 16 + 8) * Nn + colA + ni * 8;
            c0[0] = acc[mi][ni][0];
            c0[1] = acc[mi][ni][1];
            c1[0] = acc[mi][ni][2];
            c1[1] = acc[mi][ni][3];
        }
    }
}

// ---------------------------------------------------------------------------
// RoPE (in-place on g_q, g_k). Llama-style: pairs (i, i+64) within each head.
// ---------------------------------------------------------------------------
__global__ __launch_bounds__(256) void rope_kernel(float* __restrict__ q,
                                                   float* __restrict__ k) {
    int idx = blockIdx.x * blockDim.x + threadIdx.x;
    const int total = M_SZ * H_SZ * (HD_SZ / 2);
    if (idx >= total) return;

    int i = idx & 63;
    int h = (idx >> 6) & 15;
    int m = idx >> 10;
    int pos = m & (N_SZ - 1);

    float inv_freq = powf(10000.0f, -(float)i * (1.0f / 64.0f));
    float f = (float)pos * inv_freq;
    float s, c;
    sincosf(f, &s, &c);

    size_t base = (size_t)m * D_SZ + h * HD_SZ;
    float q1 = q[base + i], q2 = q[base + 64 + i];
    q[base + i]      = q1 * c - q2 * s;
    q[base + 64 + i] = q2 * c + q1 * s;

    float k1 = k[base + i], k2 = k[base + 64 + i];
    k[base + i]      = k1 * c - k2 * s;
    k[base + 64 + i] = k2 * c + k1 * s;
}

// ---------------------------------------------------------------------------
// Flash attention, fp32. Block = 256 threads (8 warps), each warp owns 4
// query rows; key tiles of 32 (one key per lane). Online softmax in-warp.
// ---------------------------------------------------------------------------
#define AT_ROWS 32
#define KT 32
#define PAD 132

__global__ __launch_bounds__(256) void attn_kernel(
    const float* __restrict__ q, const float* __restrict__ k,
    const float* __restrict__ v, float* __restrict__ o) {
    __shared__ float qs[AT_ROWS][PAD];
    __shared__ float ks[KT][PAD];
    __shared__ float vs[KT][PAD];

    const int bh = blockIdx.y;
    const int b = bh >> 4, h = bh & 15;
    const int row0 = blockIdx.x * AT_ROWS;
    const int tid = threadIdx.x;
    const int warp = tid >> 5, lane = tid & 31;

    const float* qbase = q + (size_t)(b * N_SZ + row0) * D_SZ + h * HD_SZ;
#pragma unroll
    for (int it = 0; it < 4; it++) {
        int e = tid + it * 256;
        int r = e >> 5, d4 = e & 31;
        float4 val = *(const float4*)(qbase + (size_t)r * D_SZ + d4 * 4);
        *(float4*)&qs[r][d4 * 4] = val;
    }

    float m_run[4], l_run[4], oacc[4][4];
#pragma unroll
    for (int rr = 0; rr < 4; rr++) {
        m_run[rr] = -1e30f;
        l_run[rr] = 0.0f;
#pragma unroll
        for (int d = 0; d < 4; d++) oacc[rr][d] = 0.0f;
    }

    const float scale = 0.08838834764831845f;
    const int myrow = warp * 4;

    for (int t = 0; t < N_SZ / KT; t++) {
        __syncthreads();
        const float* kbase = k + (size_t)(b * N_SZ + t * KT) * D_SZ + h * HD_SZ;
        const float* vbase = v + (size_t)(b * N_SZ + t * KT) * D_SZ + h * HD_SZ;
#pragma unroll
        for (int it = 0; it < 4; it++) {
            int e = tid + it * 256;
            int r = e >> 5, d4 = e & 31;
            *(float4*)&ks[r][d4 * 4] =
                *(const float4*)(kbase + (size_t)r * D_SZ + d4 * 4);
            *(float4*)&vs[r][d4 * 4] =
                *(const float4*)(vbase + (size_t)r * D_SZ + d4 * 4);
        }
        __syncthreads();

        float s[4] = {0.f, 0.f, 0.f, 0.f};
#pragma unroll
        for (int d4 = 0; d4 < 32; d4++) {
            float4 kf = *(const float4*)&ks[lane][d4 * 4];
#pragma unroll
            for (int rr = 0; rr < 4; rr++) {
                float4 qf = *(const float4*)&qs[myrow + rr][d4 * 4];
                s[rr] += qf.x * kf.x + qf.y * kf.y + qf.z * kf.z + qf.w * kf.w;
            }
        }

#pragma unroll
        for (int rr = 0; rr < 4; rr++) {
            float sv = s[rr] * scale;
            float mt = sv;
#pragma unroll
            for (int off = 16; off > 0; off >>= 1)
                mt = fmaxf(mt, __shfl_xor_sync(0xFFFFFFFFu, mt, off));
            float mnew = fmaxf(m_run[rr], mt);
            float corr = __expf(m_run[rr] - mnew);
            float p = __expf(sv - mnew);
            float psum = p;
#pragma unroll
            for (int off = 16; off > 0; off >>= 1)
                psum += __shfl_xor_sync(0xFFFFFFFFu, psum, off);
            l_run[rr] = l_run[rr] * corr + psum;
            m_run[rr] = mnew;
#pragma unroll
            for (int d = 0; d < 4; d++) oacc[rr][d] *= corr;
            s[rr] = p;
        }

#pragma unroll
        for (int j = 0; j < 32; j++) {
            float4 vf = *(const float4*)&vs[j][lane * 4];
#pragma unroll
            for (int rr = 0; rr < 4; rr++) {
                float pj = __shfl_sync(0xFFFFFFFFu, s[rr], j);
                oacc[rr][0] += pj * vf.x;
                oacc[rr][1] += pj * vf.y;
                oacc[rr][2] += pj * vf.z;
                oacc[rr][3] += pj * vf.w;
            }
        }
    }

#pragma unroll
    for (int rr = 0; rr < 4; rr++) {
        float inv = 1.0f / l_run[rr];
        int m = b * N_SZ + row0 + myrow + rr;
        float4 ov = make_float4(oacc[rr][0] * inv, oacc[rr][1] * inv,
                                oacc[rr][2] * inv, oacc[rr][3] * inv);
        *(float4*)(o + (size_t)m * D_SZ + h * HD_SZ + lane * 4) = ov;
    }
}

// ---------------------------------------------------------------------------
// Launch
// ---------------------------------------------------------------------------
extern "C" void kernel_launch(void* const* d_in, const int* in_sizes, int n_in,
                              void* d_out, int out_size) {
    const float* x  = (const float*)d_in[0];
    const float* Wq = (const float*)d_in[1];
    const float* Wk = (const float*)d_in[2];
    const float* Wv = (const float*)d_in[3];
    const float* Wo = (const float*)d_in[4];
    float* out = (float*)d_out;

    float *q_ptr, *k_ptr, *v_ptr, *att_ptr;
    cudaGetSymbolAddress((void**)&q_ptr, g_q);
    cudaGetSymbolAddress((void**)&k_ptr, g_k);
    cudaGetSymbolAddress((void**)&v_ptr, g_v);
    cudaGetSymbolAddress((void**)&att_ptr, g_att);

    dim3 gg(D_SZ / 128, M_SZ / 128);   // (16, 32)
    gemm_hmma<<<gg, 256>>>(x, Wq, q_ptr, D_SZ, D_SZ);
    gemm_hmma<<<gg, 256>>>(x, Wk, k_ptr, D_SZ, D_SZ);
    gemm_hmma<<<gg, 256>>>(x, Wv, v_ptr, D_SZ, D_SZ);

    int rope_total = M_SZ * H_SZ * (HD_SZ / 2);
    rope_kernel<<<(rope_total + 255) / 256, 256>>>(q_ptr, k_ptr);

    dim3 ga(N_SZ / AT_ROWS, B_SZ * H_SZ);  // (64, 32)
    attn_kernel<<<ga, 256>>>(q_ptr, k_ptr, v_ptr, att_ptr);

    gemm_hmma<<<gg, 256>>>(att_ptr, Wo, out, D_SZ, D_SZ);
}

// round 6
// speedup vs baseline: 2.7416x; 1.8280x over previous
#include <cuda_runtime.h>
#include <cuda_bf16.h>
#include <cstdint>

#define B_SZ 2
#define N_SZ 2048
#define D_SZ 2048
#define H_SZ 16
#define HD_SZ 128
#define M_SZ (B_SZ * N_SZ)   // 4096

// Scratch (static device arrays; no allocation allowed)
__device__ float g_q[M_SZ * D_SZ];
__device__ float g_k[M_SZ * D_SZ];
__device__ float g_v[M_SZ * D_SZ];
__device__ float g_att[M_SZ * D_SZ];

// ===========================================================================
// Warp-level MMA helpers (sm_80-era PTX: works at compute_103, no 'a' needed)
// ===========================================================================
__device__ __forceinline__ uint32_t smem_u32(const void* p) {
    uint32_t a;
    asm("{ .reg .u64 t; cvta.to.shared.u64 t, %1; cvt.u32.u64 %0, t; }"
        : "=r"(a) : "l"(p));
    return a;
}

__device__ __forceinline__ void ldsm_x4(uint32_t& r0, uint32_t& r1,
                                        uint32_t& r2, uint32_t& r3,
                                        uint32_t addr) {
    asm volatile("ldmatrix.sync.aligned.m8n8.x4.shared.b16 {%0,%1,%2,%3}, [%4];"
                 : "=r"(r0), "=r"(r1), "=r"(r2), "=r"(r3) : "r"(addr));
}

__device__ __forceinline__ void ldsm_x4_t(uint32_t& r0, uint32_t& r1,
                                          uint32_t& r2, uint32_t& r3,
                                          uint32_t addr) {
    asm volatile("ldmatrix.sync.aligned.m8n8.x4.trans.shared.b16 {%0,%1,%2,%3}, [%4];"
                 : "=r"(r0), "=r"(r1), "=r"(r2), "=r"(r3) : "r"(addr));
}

__device__ __forceinline__ void mma_bf16(float* d, const uint32_t* a,
                                         uint32_t b0, uint32_t b1) {
    asm volatile(
        "mma.sync.aligned.m16n8k16.row.col.f32.bf16.bf16.f32 "
        "{%0,%1,%2,%3}, {%4,%5,%6,%7}, {%8,%9}, {%0,%1,%2,%3};"
        : "+f"(d[0]), "+f"(d[1]), "+f"(d[2]), "+f"(d[3])
        : "r"(a[0]), "r"(a[1]), "r"(a[2]), "r"(a[3]), "r"(b0), "r"(b1));
}

// pack two fp32 -> bf16x2 (e0 -> low half, e1 -> high half), round-to-nearest
__device__ __forceinline__ uint32_t packbf(float e0, float e1) {
    uint32_t r;
    asm("cvt.rn.bf16x2.f32 %0, %1, %2;" : "=r"(r) : "f"(e1), "f"(e0));
    return r;
}

// Split fp32x4 -> hi/lo bf16x2 pairs
__device__ __forceinline__ void split4(float4 f, uint2& hi, uint2& lo) {
    __nv_bfloat16 h0 = __float2bfloat16(f.x);
    __nv_bfloat16 h1 = __float2bfloat16(f.y);
    __nv_bfloat16 h2 = __float2bfloat16(f.z);
    __nv_bfloat16 h3 = __float2bfloat16(f.w);
    __nv_bfloat16 l0 = __float2bfloat16(f.x - __bfloat162float(h0));
    __nv_bfloat16 l1 = __float2bfloat16(f.y - __bfloat162float(h1));
    __nv_bfloat16 l2 = __float2bfloat16(f.z - __bfloat162float(h2));
    __nv_bfloat16 l3 = __float2bfloat16(f.w - __bfloat162float(h3));
    hi.x = (uint32_t)__bfloat16_as_ushort(h0) | ((uint32_t)__bfloat16_as_ushort(h1) << 16);
    hi.y = (uint32_t)__bfloat16_as_ushort(h2) | ((uint32_t)__bfloat16_as_ushort(h3) << 16);
    lo.x = (uint32_t)__bfloat16_as_ushort(l0) | ((uint32_t)__bfloat16_as_ushort(l1) << 16);
    lo.y = (uint32_t)__bfloat16_as_ushort(l2) | ((uint32_t)__bfloat16_as_ushort(l3) << 16);
}

// Fast exp2 on the FMA pipe (y <= 0 expected; clamped below -126).
// floor-split + degree-5 poly + exponent bit-inject. rel err ~1e-6.
__device__ __forceinline__ float exp2p(float y) {
    y = fmaxf(y, -126.0f);
    int n = __float2int_rd(y);
    float f = y - (float)n;
    float r = 1.8775767e-3f;
    r = fmaf(r, f, 8.9893397e-3f);
    r = fmaf(r, f, 5.5826318e-2f);
    r = fmaf(r, f, 2.4015361e-1f);
    r = fmaf(r, f, 6.9315308e-1f);
    r = fmaf(r, f, 1.0f);
    return r * __int_as_float((n + 127) << 23);
}

#define LOG2E 1.4426950408889634f

// ===========================================================================
// HMMA GEMM: C[M, Nn] = A[M, K] @ W[Nn, K]^T  (fp32 in/out, 3x-bf16 split)
// ===========================================================================
#define BKF 32
#define RSB 40

__global__ __launch_bounds__(256) void gemm_hmma(
    const float* __restrict__ A, const float* __restrict__ W,
    float* __restrict__ C, int K, int Nn) {
    __shared__ __align__(16) uint16_t sAh[128 * RSB];
    __shared__ __align__(16) uint16_t sAl[128 * RSB];
    __shared__ __align__(16) uint16_t sBh[128 * RSB];
    __shared__ __align__(16) uint16_t sBl[128 * RSB];

    const int tid = threadIdx.x;
    const int warp = tid >> 5;
    const int lane = tid & 31;
    const int wm = warp >> 2;
    const int wn = warp & 3;
    const int mbase = wm * 64;
    const int nbase = wn * 32;

    const uint32_t uAh = smem_u32(sAh);
    const uint32_t uAl = smem_u32(sAl);
    const uint32_t uBh = smem_u32(sBh);
    const uint32_t uBl = smem_u32(sBl);

    const int lrow = tid >> 3;
    const int lc4 = tid & 7;
    const float* Abase = A + (size_t)(blockIdx.y * 128) * K;
    const float* Wbase = W + (size_t)(blockIdx.x * 128) * K;

    float acc[4][4][4];
#pragma unroll
    for (int i = 0; i < 4; i++)
#pragma unroll
        for (int j = 0; j < 4; j++)
#pragma unroll
            for (int e = 0; e < 4; e++) acc[i][j][e] = 0.0f;

    const int niter = K / BKF;
    float4 pa[4], pb[4];

#pragma unroll
    for (int it = 0; it < 4; it++) {
        int r = lrow + it * 32;
        pa[it] = *(const float4*)(Abase + (size_t)r * K + lc4 * 4);
        pb[it] = *(const float4*)(Wbase + (size_t)r * K + lc4 * 4);
    }

    for (int kc = 0; kc < niter; kc++) {
#pragma unroll
        for (int it = 0; it < 4; it++) {
            int r = lrow + it * 32;
            uint32_t off = (uint32_t)(r * 80 + lc4 * 8);
            uint2 hi, lo;
            split4(pa[it], hi, lo);
            *(uint2*)((char*)sAh + off) = hi;
            *(uint2*)((char*)sAl + off) = lo;
            split4(pb[it], hi, lo);
            *(uint2*)((char*)sBh + off) = hi;
            *(uint2*)((char*)sBl + off) = lo;
        }
        __syncthreads();

        if (kc + 1 < niter) {
            const float* An = Abase + (kc + 1) * BKF;
            const float* Wn = Wbase + (kc + 1) * BKF;
#pragma unroll
            for (int it = 0; it < 4; it++) {
                int r = lrow + it * 32;
                pa[it] = *(const float4*)(An + (size_t)r * K + lc4 * 4);
                pb[it] = *(const float4*)(Wn + (size_t)r * K + lc4 * 4);
            }
        }

        const int g = lane >> 3, lr = lane & 7;
#pragma unroll
        for (int s = 0; s < 2; s++) {
            uint32_t ah[4][4], al[4][4];
            {
                uint32_t arow = (uint32_t)(mbase + lr + ((g & 1) << 3));
                uint32_t akb  = (uint32_t)(s * 32 + ((g >> 1) << 4));
                uint32_t aoff = arow * 80 + akb;
#pragma unroll
                for (int mi = 0; mi < 4; mi++) {
                    ldsm_x4(ah[mi][0], ah[mi][1], ah[mi][2], ah[mi][3],
                            uAh + aoff + mi * (16 * 80));
                    ldsm_x4(al[mi][0], al[mi][1], al[mi][2], al[mi][3],
                            uAl + aoff + mi * (16 * 80));
                }
            }
            uint32_t bh[8], bl[8];
            {
                uint32_t brow = (uint32_t)(nbase + lr + ((g >> 1) << 3));
                uint32_t bkb  = (uint32_t)(s * 32 + ((g & 1) << 4));
                uint32_t boff = brow * 80 + bkb;
                ldsm_x4(bh[0], bh[1], bh[2], bh[3], uBh + boff);
                ldsm_x4(bh[4], bh[5], bh[6], bh[7], uBh + boff + 16 * 80);
                ldsm_x4(bl[0], bl[1], bl[2], bl[3], uBl + boff);
                ldsm_x4(bl[4], bl[5], bl[6], bl[7], uBl + boff + 16 * 80);
            }
#pragma unroll
            for (int mi = 0; mi < 4; mi++) {
#pragma unroll
                for (int ni = 0; ni < 4; ni++) {
                    mma_bf16(acc[mi][ni], ah[mi], bh[ni * 2], bh[ni * 2 + 1]);
                    mma_bf16(acc[mi][ni], ah[mi], bl[ni * 2], bl[ni * 2 + 1]);
                    mma_bf16(acc[mi][ni], al[mi], bh[ni * 2], bh[ni * 2 + 1]);
                }
            }
        }
        __syncthreads();
    }

    const int gid = lane >> 2, tig = lane & 3;
    const int rowA = blockIdx.y * 128 + mbase + gid;
    const int colA = blockIdx.x * 128 + nbase + tig * 2;
#pragma unroll
    for (int mi = 0; mi < 4; mi++) {
#pragma unroll
        for (int ni = 0; ni < 4; ni++) {
            float* c0 = C + (size_t)(rowA + mi * 16) * Nn + colA + ni * 8;
            float* c1 = C + (size_t)(rowA + mi * 16 + 8) * Nn + colA + ni * 8;
            c0[0] = acc[mi][ni][0];
            c0[1] = acc[mi][ni][1];
            c1[0] = acc[mi][ni][2];
            c1[1] = acc[mi][ni][3];
        }
    }
}

// ---------------------------------------------------------------------------
// RoPE (in-place on g_q, g_k). Llama-style: pairs (i, i+64) within each head.
// ---------------------------------------------------------------------------
__global__ __launch_bounds__(256) void rope_kernel(float* __restrict__ q,
                                                   float* __restrict__ k) {
    int idx = blockIdx.x * blockDim.x + threadIdx.x;
    const int total = M_SZ * H_SZ * (HD_SZ / 2);
    if (idx >= total) return;

    int i = idx & 63;
    int h = (idx >> 6) & 15;
    int m = idx >> 10;
    int pos = m & (N_SZ - 1);

    float inv_freq = powf(10000.0f, -(float)i * (1.0f / 64.0f));
    float f = (float)pos * inv_freq;
    float s, c;
    sincosf(f, &s, &c);

    size_t base = (size_t)m * D_SZ + h * HD_SZ;
    float q1 = q[base + i], q2 = q[base + 64 + i];
    q[base + i]      = q1 * c - q2 * s;
    q[base + 64 + i] = q2 * c + q1 * s;

    float k1 = k[base + i], k2 = k[base + 64 + i];
    k[base + i]      = k1 * c - k2 * s;
    k[base + 64 + i] = k2 * c + k1 * s;
}

// ===========================================================================
// HMMA flash attention (fp32 in/out, 3x-bf16 split everywhere).
// CTA: 256 threads (8 warps), one (b, h, 128-query tile). Key tiles of 128.
// Warp w owns query rows [w*16, w*16+16).
// SMEM tiles row stride 272 B (17 x 16B bank-groups, gcd(17,8)=1: ldmatrix
// conflict-free). Q scaled by 1/sqrt(hd) at convert time.
// ===========================================================================
#define SROW   136                        // uint16 elems per smem row
#define SROWB  272                        // bytes per smem row
#define AMAT   (128 * SROW)               // elems per matrix
#define ATT_SMEM (6 * AMAT * 2)           // 208896 bytes

__global__ __launch_bounds__(256) void attn_hmma(
    const float* __restrict__ q, const float* __restrict__ k,
    const float* __restrict__ v, float* __restrict__ o) {
    extern __shared__ uint16_t sm[];
    uint16_t* Qh = sm;
    uint16_t* Ql = sm + AMAT;
    uint16_t* Kh = sm + 2 * AMAT;
    uint16_t* Kl = sm + 3 * AMAT;
    uint16_t* Vh = sm + 4 * AMAT;
    uint16_t* Vl = sm + 5 * AMAT;
    const uint32_t uQh = smem_u32(Qh), uQl = smem_u32(Ql);
    const uint32_t uKh = smem_u32(Kh), uKl = smem_u32(Kl);
    const uint32_t uVh = smem_u32(Vh), uVl = smem_u32(Vl);

    const int bh = blockIdx.y;
    const int b = bh >> 4, h = bh & 15;
    const int q0 = blockIdx.x * 128;
    const int tid = threadIdx.x;
    const int warp = tid >> 5, lane = tid & 31;
    const int g8 = lane >> 3, lr = lane & 7;     // ldmatrix addressing
    const int g4 = lane >> 2, t4 = lane & 3;     // mma accum layout

    const float scale = 0.08838834764831845f;    // 1/sqrt(128)

    // ---- Load + scale + split Q into smem ----
    const float* qb = q + (size_t)(b * N_SZ + q0) * D_SZ + h * HD_SZ;
#pragma unroll
    for (int it = 0; it < 16; it++) {
        int e = tid + it * 256;
        int r = e >> 5, c4 = e & 31;
        float4 f = *(const float4*)(qb + (size_t)r * D_SZ + c4 * 4);
        f.x *= scale; f.y *= scale; f.z *= scale; f.w *= scale;
        uint2 hi, lo;
        split4(f, hi, lo);
        *(uint2*)((char*)Qh + r * SROWB + c4 * 8) = hi;
        *(uint2*)((char*)Ql + r * SROWB + c4 * 8) = lo;
    }

    float accO[16][4];
#pragma unroll
    for (int nd = 0; nd < 16; nd++)
#pragma unroll
        for (int e = 0; e < 4; e++) accO[nd][e] = 0.0f;
    float m0 = -1e30f, m1 = -1e30f, l0 = 0.0f, l1 = 0.0f;

    for (int kt = 0; kt < N_SZ / 128; kt++) {
        __syncthreads();   // previous iteration's ldsm reads done
        // ---- Load + split K, V tiles ----
        const float* kb = k + (size_t)(b * N_SZ + kt * 128) * D_SZ + h * HD_SZ;
        const float* vb = v + (size_t)(b * N_SZ + kt * 128) * D_SZ + h * HD_SZ;
#pragma unroll
        for (int it = 0; it < 16; it++) {
            int e = tid + it * 256;
            int r = e >> 5, c4 = e & 31;
            uint2 hi, lo;
            float4 fk = *(const float4*)(kb + (size_t)r * D_SZ + c4 * 4);
            split4(fk, hi, lo);
            *(uint2*)((char*)Kh + r * SROWB + c4 * 8) = hi;
            *(uint2*)((char*)Kl + r * SROWB + c4 * 8) = lo;
            float4 fv = *(const float4*)(vb + (size_t)r * D_SZ + c4 * 4);
            split4(fv, hi, lo);
            *(uint2*)((char*)Vh + r * SROWB + c4 * 8) = hi;
            *(uint2*)((char*)Vl + r * SROWB + c4 * 8) = lo;
        }
        __syncthreads();

        // ---- S = Q K^T (acc[nt]: key cols nt*8 + 2*t4, rows g4 / g4+8) ----
        float acc[16][4];
#pragma unroll
        for (int nt = 0; nt < 16; nt++)
#pragma unroll
            for (int e = 0; e < 4; e++) acc[nt][e] = 0.0f;

        {
            const uint32_t arow = (uint32_t)(warp * 16 + lr + ((g8 & 1) << 3));
            const uint32_t brow_g = (uint32_t)(lr + ((g8 >> 1) << 3));
#pragma unroll
            for (int ks = 0; ks < 8; ks++) {
                uint32_t acol = (uint32_t)(ks * 32 + ((g8 >> 1) << 4));
                uint32_t qh[4], ql[4];
                ldsm_x4(qh[0], qh[1], qh[2], qh[3], uQh + arow * SROWB + acol);
                ldsm_x4(ql[0], ql[1], ql[2], ql[3], uQl + arow * SROWB + acol);
                uint32_t bcol = (uint32_t)(ks * 32 + ((g8 & 1) << 4));
#pragma unroll
                for (int np = 0; np < 8; np++) {
                    uint32_t boff = (np * 16 + brow_g) * SROWB + bcol;
                    uint32_t kh[4], kl[4];
                    ldsm_x4(kh[0], kh[1], kh[2], kh[3], uKh + boff);
                    ldsm_x4(kl[0], kl[1], kl[2], kl[3], uKl + boff);
                    mma_bf16(acc[2 * np],     qh, kh[0], kh[1]);
                    mma_bf16(acc[2 * np + 1], qh, kh[2], kh[3]);
                    mma_bf16(acc[2 * np],     qh, kl[0], kl[1]);
                    mma_bf16(acc[2 * np + 1], qh, kl[2], kl[3]);
                    mma_bf16(acc[2 * np],     ql, kh[0], kh[1]);
                    mma_bf16(acc[2 * np + 1], ql, kh[2], kh[3]);
                }
            }
        }

        // ---- Online softmax (rows g4, g4+8 of this warp) ----
        float mx0 = -1e30f, mx1 = -1e30f;
#pragma unroll
        for (int nt = 0; nt < 16; nt++) {
            mx0 = fmaxf(mx0, fmaxf(acc[nt][0], acc[nt][1]));
            mx1 = fmaxf(mx1, fmaxf(acc[nt][2], acc[nt][3]));
        }
        mx0 = fmaxf(mx0, __shfl_xor_sync(0xFFFFFFFFu, mx0, 1));
        mx0 = fmaxf(mx0, __shfl_xor_sync(0xFFFFFFFFu, mx0, 2));
        mx1 = fmaxf(mx1, __shfl_xor_sync(0xFFFFFFFFu, mx1, 1));
        mx1 = fmaxf(mx1, __shfl_xor_sync(0xFFFFFFFFu, mx1, 2));
        float mn0 = fmaxf(m0, mx0), mn1 = fmaxf(m1, mx1);
        float corr0 = exp2p((m0 - mn0) * LOG2E);
        float corr1 = exp2p((m1 - mn1) * LOG2E);
        m0 = mn0; m1 = mn1;

        float sum0 = 0.0f, sum1 = 0.0f;
#pragma unroll
        for (int nt = 0; nt < 16; nt++) {
            acc[nt][0] = exp2p((acc[nt][0] - mn0) * LOG2E);
            acc[nt][1] = exp2p((acc[nt][1] - mn0) * LOG2E);
            acc[nt][2] = exp2p((acc[nt][2] - mn1) * LOG2E);
            acc[nt][3] = exp2p((acc[nt][3] - mn1) * LOG2E);
            sum0 += acc[nt][0] + acc[nt][1];
            sum1 += acc[nt][2] + acc[nt][3];
        }
        sum0 += __shfl_xor_sync(0xFFFFFFFFu, sum0, 1);
        sum0 += __shfl_xor_sync(0xFFFFFFFFu, sum0, 2);
        sum1 += __shfl_xor_sync(0xFFFFFFFFu, sum1, 1);
        sum1 += __shfl_xor_sync(0xFFFFFFFFu, sum1, 2);
        l0 = l0 * corr0 + sum0;
        l1 = l1 * corr1 + sum1;

#pragma unroll
        for (int nd = 0; nd < 16; nd++) {
            accO[nd][0] *= corr0; accO[nd][1] *= corr0;
            accO[nd][2] *= corr1; accO[nd][3] *= corr1;
        }

        // ---- O += P V  (P split hi/lo; V hi/lo from smem via trans-ldsm) ----
        const uint32_t vrow_g = (uint32_t)(lr + ((g8 & 1) << 3));
        const uint32_t vcol_g = (uint32_t)((g8 >> 1) << 4);
#pragma unroll
        for (int kk = 0; kk < 8; kk++) {
            // P A-frags from acc (ntiles 2kk, 2kk+1)
            uint32_t pah[4], pal[4];
            {
                int n0 = 2 * kk, n1 = 2 * kk + 1;
                pah[0] = packbf(acc[n0][0], acc[n0][1]);
                pah[1] = packbf(acc[n0][2], acc[n0][3]);
                pah[2] = packbf(acc[n1][0], acc[n1][1]);
                pah[3] = packbf(acc[n1][2], acc[n1][3]);
                float r00 = __int_as_float(pah[0] << 16);
                float r01 = __int_as_float(pah[0] & 0xFFFF0000u);
                float r02 = __int_as_float(pah[1] << 16);
                float r03 = __int_as_float(pah[1] & 0xFFFF0000u);
                float r10 = __int_as_float(pah[2] << 16);
                float r11 = __int_as_float(pah[2] & 0xFFFF0000u);
                float r12 = __int_as_float(pah[3] << 16);
                float r13 = __int_as_float(pah[3] & 0xFFFF0000u);
                pal[0] = packbf(acc[n0][0] - r00, acc[n0][1] - r01);
                pal[1] = packbf(acc[n0][2] - r02, acc[n0][3] - r03);
                pal[2] = packbf(acc[n1][0] - r10, acc[n1][1] - r11);
                pal[3] = packbf(acc[n1][2] - r12, acc[n1][3] - r13);
            }
            uint32_t vbase_row = (uint32_t)(kk * 16) + vrow_g;
#pragma unroll
            for (int half = 0; half < 2; half++) {
                uint32_t vh[4][4], vl[4][4];
#pragma unroll
                for (int j = 0; j < 4; j++) {
                    uint32_t ndp = half * 4 + j;   // d-pair index (16 d each)
                    uint32_t voff = vbase_row * SROWB + ndp * 32 + vcol_g;
                    ldsm_x4_t(vh[j][0], vh[j][1], vh[j][2], vh[j][3], uVh + voff);
                    ldsm_x4_t(vl[j][0], vl[j][1], vl[j][2], vl[j][3], uVl + voff);
                }
#pragma unroll
                for (int j = 0; j < 4; j++) {
                    int nda = (half * 4 + j) * 2, ndb = nda + 1;
                    mma_bf16(accO[nda], pah, vh[j][0], vh[j][1]);
                    mma_bf16(accO[ndb], pah, vh[j][2], vh[j][3]);
                    mma_bf16(accO[nda], pah, vl[j][0], vl[j][1]);
                    mma_bf16(accO[ndb], pah, vl[j][2], vl[j][3]);
                    mma_bf16(accO[nda], pal, vh[j][0], vh[j][1]);
                    mma_bf16(accO[ndb], pal, vh[j][2], vh[j][3]);
                }
            }
        }
    }

    // ---- Epilogue: normalize, write [m][h*128 + d] ----
    float inv0 = 1.0f / l0, inv1 = 1.0f / l1;
    const size_t m_row0 = (size_t)(b * N_SZ + q0 + warp * 16 + g4);
    const size_t m_row1 = m_row0 + 8;
    const int colb = h * HD_SZ + t4 * 2;
#pragma unroll
    for (int nd = 0; nd < 16; nd++) {
        float2 o0 = make_float2(accO[nd][0] * inv0, accO[nd][1] * inv0);
        float2 o1 = make_float2(accO[nd][2] * inv1, accO[nd][3] * inv1);
        *(float2*)(o + m_row0 * D_SZ + colb + nd * 8) = o0;
        *(float2*)(o + m_row1 * D_SZ + colb + nd * 8) = o1;
    }
}

// ---------------------------------------------------------------------------
// Launch
// ---------------------------------------------------------------------------
extern "C" void kernel_launch(void* const* d_in, const int* in_sizes, int n_in,
                              void* d_out, int out_size) {
    const float* x  = (const float*)d_in[0];
    const float* Wq = (const float*)d_in[1];
    const float* Wk = (const float*)d_in[2];
    const float* Wv = (const float*)d_in[3];
    const float* Wo = (const float*)d_in[4];
    float* out = (float*)d_out;

    float *q_ptr, *k_ptr, *v_ptr, *att_ptr;
    cudaGetSymbolAddress((void**)&q_ptr, g_q);
    cudaGetSymbolAddress((void**)&k_ptr, g_k);
    cudaGetSymbolAddress((void**)&v_ptr, g_v);
    cudaGetSymbolAddress((void**)&att_ptr, g_att);

    cudaFuncSetAttribute(attn_hmma, cudaFuncAttributeMaxDynamicSharedMemorySize,
                         ATT_SMEM);

    dim3 gg(D_SZ / 128, M_SZ / 128);   // (16, 32)
    gemm_hmma<<<gg, 256>>>(x, Wq, q_ptr, D_SZ, D_SZ);
    gemm_hmma<<<gg, 256>>>(x, Wk, k_ptr, D_SZ, D_SZ);
    gemm_hmma<<<gg, 256>>>(x, Wv, v_ptr, D_SZ, D_SZ);

    int rope_total = M_SZ * H_SZ * (HD_SZ / 2);
    rope_kernel<<<(rope_total + 255) / 256, 256>>>(q_ptr, k_ptr);

    dim3 ga(N_SZ / 128, B_SZ * H_SZ);  // (16, 32)
    attn_hmma<<<ga, 256, ATT_SMEM>>>(q_ptr, k_ptr, v_ptr, att_ptr);

    gemm_hmma<<<gg, 256>>>(att_ptr, Wo, out, D_SZ, D_SZ);
}

// round 7
// speedup vs baseline: 3.2024x; 1.1681x over previous
#include <cuda_runtime.h>
#include <cuda_bf16.h>
#include <cstdint>

#define B_SZ 2
#define N_SZ 2048
#define D_SZ 2048
#define H_SZ 16
#define HD_SZ 128
#define M_SZ (B_SZ * N_SZ)   // 4096

// Scratch (static device arrays; no allocation allowed)
__device__ float g_q[M_SZ * D_SZ];
__device__ float g_k[M_SZ * D_SZ];
__device__ float g_v[M_SZ * D_SZ];
__device__ __nv_bfloat16 g_xh[M_SZ * D_SZ];
__device__ __nv_bfloat16 g_xl[M_SZ * D_SZ];
__device__ __nv_bfloat16 g_wh[D_SZ * D_SZ];
__device__ __nv_bfloat16 g_wl[D_SZ * D_SZ];
__device__ __nv_bfloat16 g_oh[M_SZ * D_SZ];
__device__ __nv_bfloat16 g_ol[M_SZ * D_SZ];

// ===========================================================================
// PTX helpers (all sm_80-era: legal at compute_103)
// ===========================================================================
__device__ __forceinline__ uint32_t smem_u32(const void* p) {
    uint32_t a;
    asm("{ .reg .u64 t; cvta.to.shared.u64 t, %1; cvt.u32.u64 %0, t; }"
        : "=r"(a) : "l"(p));
    return a;
}

__device__ __forceinline__ void ldsm_x4(uint32_t& r0, uint32_t& r1,
                                        uint32_t& r2, uint32_t& r3,
                                        uint32_t addr) {
    asm volatile("ldmatrix.sync.aligned.m8n8.x4.shared.b16 {%0,%1,%2,%3}, [%4];"
                 : "=r"(r0), "=r"(r1), "=r"(r2), "=r"(r3) : "r"(addr));
}

__device__ __forceinline__ void ldsm_x4_t(uint32_t& r0, uint32_t& r1,
                                          uint32_t& r2, uint32_t& r3,
                                          uint32_t addr) {
    asm volatile("ldmatrix.sync.aligned.m8n8.x4.trans.shared.b16 {%0,%1,%2,%3}, [%4];"
                 : "=r"(r0), "=r"(r1), "=r"(r2), "=r"(r3) : "r"(addr));
}

__device__ __forceinline__ void mma_bf16(float* d, const uint32_t* a,
                                         uint32_t b0, uint32_t b1) {
    asm volatile(
        "mma.sync.aligned.m16n8k16.row.col.f32.bf16.bf16.f32 "
        "{%0,%1,%2,%3}, {%4,%5,%6,%7}, {%8,%9}, {%0,%1,%2,%3};"
        : "+f"(d[0]), "+f"(d[1]), "+f"(d[2]), "+f"(d[3])
        : "r"(a[0]), "r"(a[1]), "r"(a[2]), "r"(a[3]), "r"(b0), "r"(b1));
}

#define CP_ASYNC16(saddr, gptr) \
    asm volatile("cp.async.cg.shared.global [%0], [%1], 16;" \
                 :: "r"(saddr), "l"(gptr))
#define CP_COMMIT() asm volatile("cp.async.commit_group;")
#define CP_WAIT(n)  asm volatile("cp.async.wait_group %0;" :: "n"(n))

// pack two fp32 -> bf16x2 (e0 low, e1 high)
__device__ __forceinline__ uint32_t packbf(float e0, float e1) {
    uint32_t r;
    asm("cvt.rn.bf16x2.f32 %0, %1, %2;" : "=r"(r) : "f"(e1), "f"(e0));
    return r;
}

// Split fp32x4 -> hi/lo bf16x2 pairs
__device__ __forceinline__ void split4(float4 f, uint2& hi, uint2& lo) {
    hi.x = packbf(f.x, f.y);
    hi.y = packbf(f.z, f.w);
    float h0 = __int_as_float(hi.x << 16);
    float h1 = __int_as_float(hi.x & 0xFFFF0000u);
    float h2 = __int_as_float(hi.y << 16);
    float h3 = __int_as_float(hi.y & 0xFFFF0000u);
    lo.x = packbf(f.x - h0, f.y - h1);
    lo.y = packbf(f.z - h2, f.w - h3);
}

// split two fp32 to hi/lo bf16x2 words
__device__ __forceinline__ void split2(float e0, float e1,
                                       uint32_t& h, uint32_t& l) {
    h = packbf(e0, e1);
    float h0 = __int_as_float(h << 16);
    float h1 = __int_as_float(h & 0xFFFF0000u);
    l = packbf(e0 - h0, e1 - h1);
}

// Fast exp2 on the FMA pipe
__device__ __forceinline__ float exp2p(float y) {
    y = fmaxf(y, -126.0f);
    int n = __float2int_rd(y);
    float f = y - (float)n;
    float r = 1.8775767e-3f;
    r = fmaf(r, f, 8.9893397e-3f);
    r = fmaf(r, f, 5.5826318e-2f);
    r = fmaf(r, f, 2.4015361e-1f);
    r = fmaf(r, f, 6.9315308e-1f);
    r = fmaf(r, f, 1.0f);
    return r * __int_as_float((n + 127) << 23);
}

#define LOG2E 1.4426950408889634f

// ===========================================================================
// Split kernel: fp32 array -> hi/lo bf16 arrays
// ===========================================================================
__global__ __launch_bounds__(256) void split_kernel(
    const float4* __restrict__ src, uint2* __restrict__ hi,
    uint2* __restrict__ lo, int n4) {
    int i = blockIdx.x * blockDim.x + threadIdx.x;
    if (i >= n4) return;
    uint2 h, l;
    split4(src[i], h, l);
    hi[i] = h;
    lo[i] = l;
}

// ===========================================================================
// HMMA GEMM v2: C[M,Nn] = A @ W^T with pre-split bf16 hi/lo inputs,
// cp.async double-buffered. CTA tile 128x128, BK=32, 256 threads, 8 warps.
// SMEM: 2 stages x 4 arrays x (128 rows x 80 B) = 81920 B dynamic.
// ===========================================================================
#define RSTRIDE 80                         // bytes per smem row
#define ARR_B  (128 * RSTRIDE)             // 10240 bytes per array
#define STAGE_B (4 * ARR_B)                // 40960 bytes per stage
#define G3_SMEM (2 * STAGE_B)              // 81920

__global__ __launch_bounds__(256) void gemm3(
    const __nv_bfloat16* __restrict__ Ah, const __nv_bfloat16* __restrict__ Al,
    const __nv_bfloat16* __restrict__ Bh, const __nv_bfloat16* __restrict__ Bl,
    float* __restrict__ C, int K, int Nn) {
    extern __shared__ char dsm[];
    const uint32_t sb = smem_u32(dsm);

    const int tid = threadIdx.x;
    const int warp = tid >> 5;
    const int lane = tid & 31;
    const int mbase = (warp >> 2) * 64;
    const int nbase = (warp & 3) * 32;

    const size_t arow_g = (size_t)(blockIdx.y * 128);
    const size_t brow_gg = (size_t)(blockIdx.x * 128);

    // cp.async mapping: chunk c in [0,512) per array: row=c>>2, col16=c&3
    const int c1 = tid, c2 = tid + 256;
    const int r1 = c1 >> 2, f1 = c1 & 3;
    const int r2 = c2 >> 2, f2 = c2 & 3;

    float acc[4][4][4];
#pragma unroll
    for (int i = 0; i < 4; i++)
#pragma unroll
        for (int j = 0; j < 4; j++)
#pragma unroll
            for (int e = 0; e < 4; e++) acc[i][j][e] = 0.0f;

    const int niter = K / 32;

    auto prefetch = [&](int stage, int kc) {
        uint32_t s0 = sb + stage * STAGE_B;
        const __nv_bfloat16* pAh = Ah + (arow_g)*K + kc * 32;
        const __nv_bfloat16* pAl = Al + (arow_g)*K + kc * 32;
        const __nv_bfloat16* pBh = Bh + (brow_gg)*K + kc * 32;
        const __nv_bfloat16* pBl = Bl + (brow_gg)*K + kc * 32;
        uint32_t o1 = (uint32_t)(r1 * RSTRIDE + f1 * 16);
        uint32_t o2 = (uint32_t)(r2 * RSTRIDE + f2 * 16);
        size_t g1 = (size_t)r1 * K + f1 * 8;
        size_t g2 = (size_t)r2 * K + f2 * 8;
        CP_ASYNC16(s0 + o1,              pAh + g1);
        CP_ASYNC16(s0 + o2,              pAh + g2);
        CP_ASYNC16(s0 + ARR_B + o1,      pAl + g1);
        CP_ASYNC16(s0 + ARR_B + o2,      pAl + g2);
        CP_ASYNC16(s0 + 2 * ARR_B + o1,  pBh + g1);
        CP_ASYNC16(s0 + 2 * ARR_B + o2,  pBh + g2);
        CP_ASYNC16(s0 + 3 * ARR_B + o1,  pBl + g1);
        CP_ASYNC16(s0 + 3 * ARR_B + o2,  pBl + g2);
    };

    prefetch(0, 0);
    CP_COMMIT();

    const int g = lane >> 3, lr = lane & 7;
    for (int kc = 0; kc < niter; kc++) {
        int cur = kc & 1;
        if (kc + 1 < niter) {
            prefetch(cur ^ 1, kc + 1);
            CP_COMMIT();
            CP_WAIT(1);
        } else {
            CP_WAIT(0);
        }
        __syncthreads();

        const uint32_t uAh = sb + cur * STAGE_B;
        const uint32_t uAl = uAh + ARR_B;
        const uint32_t uBh = uAh + 2 * ARR_B;
        const uint32_t uBl = uAh + 3 * ARR_B;

#pragma unroll
        for (int s = 0; s < 2; s++) {
            uint32_t ah[4][4], al[4][4];
            {
                uint32_t arow = (uint32_t)(mbase + lr + ((g & 1) << 3));
                uint32_t akb  = (uint32_t)(s * 32 + ((g >> 1) << 4));
                uint32_t aoff = arow * RSTRIDE + akb;
#pragma unroll
                for (int mi = 0; mi < 4; mi++) {
                    ldsm_x4(ah[mi][0], ah[mi][1], ah[mi][2], ah[mi][3],
                            uAh + aoff + mi * (16 * RSTRIDE));
                    ldsm_x4(al[mi][0], al[mi][1], al[mi][2], al[mi][3],
                            uAl + aoff + mi * (16 * RSTRIDE));
                }
            }
            uint32_t bh[8], bl[8];
            {
                uint32_t brow = (uint32_t)(nbase + lr + ((g >> 1) << 3));
                uint32_t bkb  = (uint32_t)(s * 32 + ((g & 1) << 4));
                uint32_t boff = brow * RSTRIDE + bkb;
                ldsm_x4(bh[0], bh[1], bh[2], bh[3], uBh + boff);
                ldsm_x4(bh[4], bh[5], bh[6], bh[7], uBh + boff + 16 * RSTRIDE);
                ldsm_x4(bl[0], bl[1], bl[2], bl[3], uBl + boff);
                ldsm_x4(bl[4], bl[5], bl[6], bl[7], uBl + boff + 16 * RSTRIDE);
            }
#pragma unroll
            for (int mi = 0; mi < 4; mi++) {
#pragma unroll
                for (int ni = 0; ni < 4; ni++) {
                    mma_bf16(acc[mi][ni], ah[mi], bh[ni * 2], bh[ni * 2 + 1]);
                    mma_bf16(acc[mi][ni], ah[mi], bl[ni * 2], bl[ni * 2 + 1]);
                    mma_bf16(acc[mi][ni], al[mi], bh[ni * 2], bh[ni * 2 + 1]);
                }
            }
        }
        __syncthreads();
    }

    const int gid = lane >> 2, tig = lane & 3;
    const int rowA = blockIdx.y * 128 + mbase + gid;
    const int colA = blockIdx.x * 128 + nbase + tig * 2;
#pragma unroll
    for (int mi = 0; mi < 4; mi++) {
#pragma unroll
        for (int ni = 0; ni < 4; ni++) {
            float* c0 = C + (size_t)(rowA + mi * 16) * Nn + colA + ni * 8;
            float* c1 = C + (size_t)(rowA + mi * 16 + 8) * Nn + colA + ni * 8;
            c0[0] = acc[mi][ni][0];
            c0[1] = acc[mi][ni][1];
            c1[0] = acc[mi][ni][2];
            c1[1] = acc[mi][ni][3];
        }
    }
}

// ---------------------------------------------------------------------------
// RoPE (in-place on g_q, g_k)
// ---------------------------------------------------------------------------
__global__ __launch_bounds__(256) void rope_kernel(float* __restrict__ q,
                                                   float* __restrict__ k) {
    int idx = blockIdx.x * blockDim.x + threadIdx.x;
    const int total = M_SZ * H_SZ * (HD_SZ / 2);
    if (idx >= total) return;

    int i = idx & 63;
    int h = (idx >> 6) & 15;
    int m = idx >> 10;
    int pos = m & (N_SZ - 1);

    float inv_freq = powf(10000.0f, -(float)i * (1.0f / 64.0f));
    float f = (float)pos * inv_freq;
    float s, c;
    sincosf(f, &s, &c);

    size_t base = (size_t)m * D_SZ + h * HD_SZ;
    float q1 = q[base + i], q2 = q[base + 64 + i];
    q[base + i]      = q1 * c - q2 * s;
    q[base + 64 + i] = q2 * c + q1 * s;

    float k1 = k[base + i], k2 = k[base + 64 + i];
    k[base + i]      = k1 * c - k2 * s;
    k[base + 64 + i] = k2 * c + k1 * s;
}

// ===========================================================================
// HMMA flash attention. Same as R6 kernel, but epilogue writes O directly as
// hi/lo bf16 (for the O-projection GEMM).
// ===========================================================================
#define SROW   136
#define SROWB  272
#define AMAT   (128 * SROW)
#define ATT_SMEM (6 * AMAT * 2)

__global__ __launch_bounds__(256) void attn_hmma(
    const float* __restrict__ q, const float* __restrict__ k,
    const float* __restrict__ v,
    __nv_bfloat16* __restrict__ oh, __nv_bfloat16* __restrict__ ol) {
    extern __shared__ uint16_t sm[];
    uint16_t* Qh = sm;
    uint16_t* Ql = sm + AMAT;
    uint16_t* Kh = sm + 2 * AMAT;
    uint16_t* Kl = sm + 3 * AMAT;
    uint16_t* Vh = sm + 4 * AMAT;
    uint16_t* Vl = sm + 5 * AMAT;
    const uint32_t uQh = smem_u32(Qh), uQl = smem_u32(Ql);
    const uint32_t uKh = smem_u32(Kh), uKl = smem_u32(Kl);
    const uint32_t uVh = smem_u32(Vh), uVl = smem_u32(Vl);

    const int bh = blockIdx.y;
    const int b = bh >> 4, h = bh & 15;
    const int q0 = blockIdx.x * 128;
    const int tid = threadIdx.x;
    const int warp = tid >> 5, lane = tid & 31;
    const int g8 = lane >> 3, lr = lane & 7;
    const int g4 = lane >> 2, t4 = lane & 3;

    const float scale = 0.08838834764831845f;

    const float* qb = q + (size_t)(b * N_SZ + q0) * D_SZ + h * HD_SZ;
#pragma unroll
    for (int it = 0; it < 16; it++) {
        int e = tid + it * 256;
        int r = e >> 5, c4 = e & 31;
        float4 f = *(const float4*)(qb + (size_t)r * D_SZ + c4 * 4);
        f.x *= scale; f.y *= scale; f.z *= scale; f.w *= scale;
        uint2 hi, lo;
        split4(f, hi, lo);
        *(uint2*)((char*)Qh + r * SROWB + c4 * 8) = hi;
        *(uint2*)((char*)Ql + r * SROWB + c4 * 8) = lo;
    }

    float accO[16][4];
#pragma unroll
    for (int nd = 0; nd < 16; nd++)
#pragma unroll
        for (int e = 0; e < 4; e++) accO[nd][e] = 0.0f;
    float m0 = -1e30f, m1 = -1e30f, l0 = 0.0f, l1 = 0.0f;

    for (int kt = 0; kt < N_SZ / 128; kt++) {
        __syncthreads();
        const float* kb = k + (size_t)(b * N_SZ + kt * 128) * D_SZ + h * HD_SZ;
        const float* vb = v + (size_t)(b * N_SZ + kt * 128) * D_SZ + h * HD_SZ;
#pragma unroll
        for (int it = 0; it < 16; it++) {
            int e = tid + it * 256;
            int r = e >> 5, c4 = e & 31;
            uint2 hi, lo;
            float4 fk = *(const float4*)(kb + (size_t)r * D_SZ + c4 * 4);
            split4(fk, hi, lo);
            *(uint2*)((char*)Kh + r * SROWB + c4 * 8) = hi;
            *(uint2*)((char*)Kl + r * SROWB + c4 * 8) = lo;
            float4 fv = *(const float4*)(vb + (size_t)r * D_SZ + c4 * 4);
            split4(fv, hi, lo);
            *(uint2*)((char*)Vh + r * SROWB + c4 * 8) = hi;
            *(uint2*)((char*)Vl + r * SROWB + c4 * 8) = lo;
        }
        __syncthreads();

        float acc[16][4];
#pragma unroll
        for (int nt = 0; nt < 16; nt++)
#pragma unroll
            for (int e = 0; e < 4; e++) acc[nt][e] = 0.0f;

        {
            const uint32_t arow = (uint32_t)(warp * 16 + lr + ((g8 & 1) << 3));
            const uint32_t brow_g = (uint32_t)(lr + ((g8 >> 1) << 3));
#pragma unroll
            for (int ks = 0; ks < 8; ks++) {
                uint32_t acol = (uint32_t)(ks * 32 + ((g8 >> 1) << 4));
                uint32_t qh[4], ql[4];
                ldsm_x4(qh[0], qh[1], qh[2], qh[3], uQh + arow * SROWB + acol);
                ldsm_x4(ql[0], ql[1], ql[2], ql[3], uQl + arow * SROWB + acol);
                uint32_t bcol = (uint32_t)(ks * 32 + ((g8 & 1) << 4));
#pragma unroll
                for (int np = 0; np < 8; np++) {
                    uint32_t boff = (np * 16 + brow_g) * SROWB + bcol;
                    uint32_t kh[4], kl[4];
                    ldsm_x4(kh[0], kh[1], kh[2], kh[3], uKh + boff);
                    ldsm_x4(kl[0], kl[1], kl[2], kl[3], uKl + boff);
                    mma_bf16(acc[2 * np],     qh, kh[0], kh[1]);
                    mma_bf16(acc[2 * np + 1], qh, kh[2], kh[3]);
                    mma_bf16(acc[2 * np],     qh, kl[0], kl[1]);
                    mma_bf16(acc[2 * np + 1], qh, kl[2], kl[3]);
                    mma_bf16(acc[2 * np],     ql, kh[0], kh[1]);
                    mma_bf16(acc[2 * np + 1], ql, kh[2], kh[3]);
                }
            }
        }

        float mx0 = -1e30f, mx1 = -1e30f;
#pragma unroll
        for (int nt = 0; nt < 16; nt++) {
            mx0 = fmaxf(mx0, fmaxf(acc[nt][0], acc[nt][1]));
            mx1 = fmaxf(mx1, fmaxf(acc[nt][2], acc[nt][3]));
        }
        mx0 = fmaxf(mx0, __shfl_xor_sync(0xFFFFFFFFu, mx0, 1));
        mx0 = fmaxf(mx0, __shfl_xor_sync(0xFFFFFFFFu, mx0, 2));
        mx1 = fmaxf(mx1, __shfl_xor_sync(0xFFFFFFFFu, mx1, 1));
        mx1 = fmaxf(mx1, __shfl_xor_sync(0xFFFFFFFFu, mx1, 2));
        float mn0 = fmaxf(m0, mx0), mn1 = fmaxf(m1, mx1);
        float corr0 = exp2p((m0 - mn0) * LOG2E);
        float corr1 = exp2p((m1 - mn1) * LOG2E);
        m0 = mn0; m1 = mn1;

        float sum0 = 0.0f, sum1 = 0.0f;
#pragma unroll
        for (int nt = 0; nt < 16; nt++) {
            acc[nt][0] = exp2p((acc[nt][0] - mn0) * LOG2E);
            acc[nt][1] = exp2p((acc[nt][1] - mn0) * LOG2E);
            acc[nt][2] = exp2p((acc[nt][2] - mn1) * LOG2E);
            acc[nt][3] = exp2p((acc[nt][3] - mn1) * LOG2E);
            sum0 += acc[nt][0] + acc[nt][1];
            sum1 += acc[nt][2] + acc[nt][3];
        }
        sum0 += __shfl_xor_sync(0xFFFFFFFFu, sum0, 1);
        sum0 += __shfl_xor_sync(0xFFFFFFFFu, sum0, 2);
        sum1 += __shfl_xor_sync(0xFFFFFFFFu, sum1, 1);
        sum1 += __shfl_xor_sync(0xFFFFFFFFu, sum1, 2);
        l0 = l0 * corr0 + sum0;
        l1 = l1 * corr1 + sum1;

#pragma unroll
        for (int nd = 0; nd < 16; nd++) {
            accO[nd][0] *= corr0; accO[nd][1] *= corr0;
            accO[nd][2] *= corr1; accO[nd][3] *= corr1;
        }

        const uint32_t vrow_g = (uint32_t)(lr + ((g8 & 1) << 3));
        const uint32_t vcol_g = (uint32_t)((g8 >> 1) << 4);
#pragma unroll
        for (int kk = 0; kk < 8; kk++) {
            uint32_t pah[4], pal[4];
            {
                int n0 = 2 * kk, n1 = 2 * kk + 1;
                split2(acc[n0][0], acc[n0][1], pah[0], pal[0]);
                split2(acc[n0][2], acc[n0][3], pah[1], pal[1]);
                split2(acc[n1][0], acc[n1][1], pah[2], pal[2]);
                split2(acc[n1][2], acc[n1][3], pah[3], pal[3]);
            }
            uint32_t vbase_row = (uint32_t)(kk * 16) + vrow_g;
#pragma unroll
            for (int half = 0; half < 2; half++) {
                uint32_t vh[4][4], vl[4][4];
#pragma unroll
                for (int j = 0; j < 4; j++) {
                    uint32_t ndp = half * 4 + j;
                    uint32_t voff = vbase_row * SROWB + ndp * 32 + vcol_g;
                    ldsm_x4_t(vh[j][0], vh[j][1], vh[j][2], vh[j][3], uVh + voff);
                    ldsm_x4_t(vl[j][0], vl[j][1], vl[j][2], vl[j][3], uVl + voff);
                }
#pragma unroll
                for (int j = 0; j < 4; j++) {
                    int nda = (half * 4 + j) * 2, ndb = nda + 1;
                    mma_bf16(accO[nda], pah, vh[j][0], vh[j][1]);
                    mma_bf16(accO[ndb], pah, vh[j][2], vh[j][3]);
                    mma_bf16(accO[nda], pah, vl[j][0], vl[j][1]);
                    mma_bf16(accO[ndb], pah, vl[j][2], vl[j][3]);
                    mma_bf16(accO[nda], pal, vh[j][0], vh[j][1]);
                    mma_bf16(accO[ndb], pal, vh[j][2], vh[j][3]);
                }
            }
        }
    }

    // ---- Epilogue: normalize, split to hi/lo bf16, write ----
    float inv0 = 1.0f / l0, inv1 = 1.0f / l1;
    const size_t m_row0 = (size_t)(b * N_SZ + q0 + warp * 16 + g4);
    const size_t m_row1 = m_row0 + 8;
    const int colb = h * HD_SZ + t4 * 2;
#pragma unroll
    for (int nd = 0; nd < 16; nd++) {
        uint32_t hw, lw;
        split2(accO[nd][0] * inv0, accO[nd][1] * inv0, hw, lw);
        *(uint32_t*)(oh + m_row0 * D_SZ + colb + nd * 8) = hw;
        *(uint32_t*)(ol + m_row0 * D_SZ + colb + nd * 8) = lw;
        split2(accO[nd][2] * inv1, accO[nd][3] * inv1, hw, lw);
        *(uint32_t*)(oh + m_row1 * D_SZ + colb + nd * 8) = hw;
        *(uint32_t*)(ol + m_row1 * D_SZ + colb + nd * 8) = lw;
    }
}

// ---------------------------------------------------------------------------
// Launch
// ---------------------------------------------------------------------------
extern "C" void kernel_launch(void* const* d_in, const int* in_sizes, int n_in,
                              void* d_out, int out_size) {
    const float* x  = (const float*)d_in[0];
    const float* Wq = (const float*)d_in[1];
    const float* Wk = (const float*)d_in[2];
    const float* Wv = (const float*)d_in[3];
    const float* Wo = (const float*)d_in[4];
    float* out = (float*)d_out;

    float *q_ptr, *k_ptr, *v_ptr;
    __nv_bfloat16 *xh, *xl, *wh, *wl, *oh, *ol;
    cudaGetSymbolAddress((void**)&q_ptr, g_q);
    cudaGetSymbolAddress((void**)&k_ptr, g_k);
    cudaGetSymbolAddress((void**)&v_ptr, g_v);
    cudaGetSymbolAddress((void**)&xh, g_xh);
    cudaGetSymbolAddress((void**)&xl, g_xl);
    cudaGetSymbolAddress((void**)&wh, g_wh);
    cudaGetSymbolAddress((void**)&wl, g_wl);
    cudaGetSymbolAddress((void**)&oh, g_oh);
    cudaGetSymbolAddress((void**)&ol, g_ol);

    cudaFuncSetAttribute(gemm3, cudaFuncAttributeMaxDynamicSharedMemorySize,
                         G3_SMEM);
    cudaFuncSetAttribute(attn_hmma, cudaFuncAttributeMaxDynamicSharedMemorySize,
                         ATT_SMEM);

    const int nx4 = M_SZ * D_SZ / 4;       // x / att elems in float4
    const int nw4 = D_SZ * D_SZ / 4;       // weight elems in float4
    dim3 gg(D_SZ / 128, M_SZ / 128);       // (16, 32)

    // x -> bf16 hi/lo (used by Q, K, V projections)
    split_kernel<<<nx4 / 256, 256>>>((const float4*)x, (uint2*)xh, (uint2*)xl, nx4);

    // Q/K/V projections (weight buffer reused; stream order serializes)
    split_kernel<<<nw4 / 256, 256>>>((const float4*)Wq, (uint2*)wh, (uint2*)wl, nw4);
    gemm3<<<gg, 256, G3_SMEM>>>(xh, xl, wh, wl, q_ptr, D_SZ, D_SZ);
    split_kernel<<<nw4 / 256, 256>>>((const float4*)Wk, (uint2*)wh, (uint2*)wl, nw4);
    gemm3<<<gg, 256, G3_SMEM>>>(xh, xl, wh, wl, k_ptr, D_SZ, D_SZ);
    split_kernel<<<nw4 / 256, 256>>>((const float4*)Wv, (uint2*)wh, (uint2*)wl, nw4);
    gemm3<<<gg, 256, G3_SMEM>>>(xh, xl, wh, wl, v_ptr, D_SZ, D_SZ);

    int rope_total = M_SZ * H_SZ * (HD_SZ / 2);
    rope_kernel<<<(rope_total + 255) / 256, 256>>>(q_ptr, k_ptr);

    dim3 ga(N_SZ / 128, B_SZ * H_SZ);      // (16, 32)
    attn_hmma<<<ga, 256, ATT_SMEM>>>(q_ptr, k_ptr, v_ptr, oh, ol);

    // O projection: attention output already split
    split_kernel<<<nw4 / 256, 256>>>((const float4*)Wo, (uint2*)wh, (uint2*)wl, nw4);
    gemm3<<<gg, 256, G3_SMEM>>>(oh, ol, wh, wl, out, D_SZ, D_SZ);
}

// round 8
// speedup vs baseline: 3.4132x; 1.0658x over previous
#include <cuda_runtime.h>
#include <cuda_bf16.h>
#include <cstdint>

#define B_SZ 2
#define N_SZ 2048
#define D_SZ 2048
#define H_SZ 16
#define HD_SZ 128
#define M_SZ (B_SZ * N_SZ)   // 4096

// Scratch (static device arrays; no allocation allowed)
__device__ float g_q[M_SZ * D_SZ];
__device__ float g_k[M_SZ * D_SZ];
__device__ float g_v[M_SZ * D_SZ];
__device__ __nv_bfloat16 g_xh[M_SZ * D_SZ];
__device__ __nv_bfloat16 g_xl[M_SZ * D_SZ];
__device__ __nv_bfloat16 g_wh[4 * D_SZ * D_SZ];
__device__ __nv_bfloat16 g_wl[4 * D_SZ * D_SZ];
__device__ __nv_bfloat16 g_oh[M_SZ * D_SZ];
__device__ __nv_bfloat16 g_ol[M_SZ * D_SZ];

// ===========================================================================
// PTX helpers (all sm_80-era: legal at compute_103)
// ===========================================================================
__device__ __forceinline__ uint32_t smem_u32(const void* p) {
    uint32_t a;
    asm("{ .reg .u64 t; cvta.to.shared.u64 t, %1; cvt.u32.u64 %0, t; }"
        : "=r"(a) : "l"(p));
    return a;
}

__device__ __forceinline__ void ldsm_x4(uint32_t& r0, uint32_t& r1,
                                        uint32_t& r2, uint32_t& r3,
                                        uint32_t addr) {
    asm volatile("ldmatrix.sync.aligned.m8n8.x4.shared.b16 {%0,%1,%2,%3}, [%4];"
                 : "=r"(r0), "=r"(r1), "=r"(r2), "=r"(r3) : "r"(addr));
}

__device__ __forceinline__ void ldsm_x4_t(uint32_t& r0, uint32_t& r1,
                                          uint32_t& r2, uint32_t& r3,
                                          uint32_t addr) {
    asm volatile("ldmatrix.sync.aligned.m8n8.x4.trans.shared.b16 {%0,%1,%2,%3}, [%4];"
                 : "=r"(r0), "=r"(r1), "=r"(r2), "=r"(r3) : "r"(addr));
}

__device__ __forceinline__ void mma_bf16(float* d, const uint32_t* a,
                                         uint32_t b0, uint32_t b1) {
    asm volatile(
        "mma.sync.aligned.m16n8k16.row.col.f32.bf16.bf16.f32 "
        "{%0,%1,%2,%3}, {%4,%5,%6,%7}, {%8,%9}, {%0,%1,%2,%3};"
        : "+f"(d[0]), "+f"(d[1]), "+f"(d[2]), "+f"(d[3])
        : "r"(a[0]), "r"(a[1]), "r"(a[2]), "r"(a[3]), "r"(b0), "r"(b1));
}

#define CP_ASYNC16(saddr, gptr) \
    asm volatile("cp.async.cg.shared.global [%0], [%1], 16;" \
                 :: "r"(saddr), "l"(gptr))
#define CP_COMMIT() asm volatile("cp.async.commit_group;")
#define CP_WAIT(n)  asm volatile("cp.async.wait_group %0;" :: "n"(n))

// pack two fp32 -> bf16x2 (e0 low, e1 high)
__device__ __forceinline__ uint32_t packbf(float e0, float e1) {
    uint32_t r;
    asm("cvt.rn.bf16x2.f32 %0, %1, %2;" : "=r"(r) : "f"(e1), "f"(e0));
    return r;
}

// Split fp32x4 -> hi/lo bf16x2 pairs
__device__ __forceinline__ void split4(float4 f, uint2& hi, uint2& lo) {
    hi.x = packbf(f.x, f.y);
    hi.y = packbf(f.z, f.w);
    float h0 = __int_as_float(hi.x << 16);
    float h1 = __int_as_float(hi.x & 0xFFFF0000u);
    float h2 = __int_as_float(hi.y << 16);
    float h3 = __int_as_float(hi.y & 0xFFFF0000u);
    lo.x = packbf(f.x - h0, f.y - h1);
    lo.y = packbf(f.z - h2, f.w - h3);
}

// split two fp32 to hi/lo bf16x2 words
__device__ __forceinline__ void split2(float e0, float e1,
                                       uint32_t& h, uint32_t& l) {
    h = packbf(e0, e1);
    float h0 = __int_as_float(h << 16);
    float h1 = __int_as_float(h & 0xFFFF0000u);
    l = packbf(e0 - h0, e1 - h1);
}

// Fast exp2 on the FMA pipe
__device__ __forceinline__ float exp2p(float y) {
    y = fmaxf(y, -126.0f);
    int n = __float2int_rd(y);
    float f = y - (float)n;
    float r = 1.8775767e-3f;
    r = fmaf(r, f, 8.9893397e-3f);
    r = fmaf(r, f, 5.5826318e-2f);
    r = fmaf(r, f, 2.4015361e-1f);
    r = fmaf(r, f, 6.9315308e-1f);
    r = fmaf(r, f, 1.0f);
    return r * __int_as_float((n + 127) << 23);
}

#define LOG2E 1.4426950408889634f

// ===========================================================================
// Split kernel: fp32 array -> hi/lo bf16 arrays
// ===========================================================================
__global__ __launch_bounds__(256) void split_kernel(
    const float4* __restrict__ src, uint2* __restrict__ hi,
    uint2* __restrict__ lo, int n4) {
    int i = blockIdx.x * blockDim.x + threadIdx.x;
    if (i >= n4) return;
    uint2 h, l;
    split4(src[i], h, l);
    hi[i] = h;
    lo[i] = l;
}

// ===========================================================================
// HMMA GEMM v3: C[M,Nn] = A @ W^T, pre-split bf16 hi/lo, cp.async 2-stage,
// BK=64 (192 MMAs per warp per barrier). CTA tile 128x128, 256 thr, 8 warps.
// gridDim.z selects weight slice (z*Nn*K) and output {C0, C1, C2}.
// SMEM rows stride 144 B (9 x 16B groups, gcd(9,8)=1 -> ldmatrix clean).
// ===========================================================================
#define RS4    144
#define ARR4   (128 * RS4)            // 18432 B
#define STAGE4 (4 * ARR4)             // 73728 B
#define G4_SMEM (2 * STAGE4)          // 147456 B

__global__ __launch_bounds__(256) void gemm4(
    const __nv_bfloat16* __restrict__ Ah, const __nv_bfloat16* __restrict__ Al,
    const __nv_bfloat16* __restrict__ Wh, const __nv_bfloat16* __restrict__ Wl,
    float* __restrict__ C0, float* __restrict__ C1, float* __restrict__ C2,
    int K, int Nn) {
    extern __shared__ char dsm[];
    const uint32_t sb = smem_u32(dsm);

    const int tid = threadIdx.x;
    const int warp = tid >> 5;
    const int lane = tid & 31;
    const int mbase = (warp >> 2) * 64;
    const int nbase = (warp & 3) * 32;

    const int z = blockIdx.z;
    float* C = (z == 0) ? C0 : (z == 1) ? C1 : C2;
    const __nv_bfloat16* Whz = Wh + (size_t)z * Nn * K;
    const __nv_bfloat16* Wlz = Wl + (size_t)z * Nn * K;

    const size_t arow_g = (size_t)(blockIdx.y * 128);
    const size_t brow_g = (size_t)(blockIdx.x * 128);

    // cp.async mapping: per array 1024 chunks of 16B; chunk c: row=c>>3, f=c&7
    float acc[4][4][4];
#pragma unroll
    for (int i = 0; i < 4; i++)
#pragma unroll
        for (int j = 0; j < 4; j++)
#pragma unroll
            for (int e = 0; e < 4; e++) acc[i][j][e] = 0.0f;

    const int niter = K / 64;   // 32

    const __nv_bfloat16* gbase[4];
    gbase[0] = Ah + arow_g * K;
    gbase[1] = Al + arow_g * K;
    gbase[2] = Whz + brow_g * K;
    gbase[3] = Wlz + brow_g * K;

    auto prefetch = [&](int stage, int kc) {
        uint32_t s0 = sb + stage * STAGE4;
#pragma unroll
        for (int a = 0; a < 4; a++) {
            const __nv_bfloat16* gp = gbase[a] + kc * 64;
            uint32_t sa = s0 + a * ARR4;
#pragma unroll
            for (int cc = 0; cc < 4; cc++) {
                int c = tid + cc * 256;
                int r = c >> 3, f = c & 7;
                CP_ASYNC16(sa + (uint32_t)(r * RS4 + f * 16),
                           gp + (size_t)r * K + f * 8);
            }
        }
    };

    prefetch(0, 0);
    CP_COMMIT();

    const int g = lane >> 3, lr = lane & 7;
    for (int kc = 0; kc < niter; kc++) {
        int cur = kc & 1;
        if (kc + 1 < niter) {
            prefetch(cur ^ 1, kc + 1);
            CP_COMMIT();
            CP_WAIT(1);
        } else {
            CP_WAIT(0);
        }
        __syncthreads();

        const uint32_t uAh = sb + cur * STAGE4;
        const uint32_t uAl = uAh + ARR4;
        const uint32_t uBh = uAh + 2 * ARR4;
        const uint32_t uBl = uAh + 3 * ARR4;

#pragma unroll
        for (int s = 0; s < 4; s++) {
            uint32_t ah[4][4], al[4][4];
            {
                uint32_t arow = (uint32_t)(mbase + lr + ((g & 1) << 3));
                uint32_t akb  = (uint32_t)(s * 32 + ((g >> 1) << 4));
                uint32_t aoff = arow * RS4 + akb;
#pragma unroll
                for (int mi = 0; mi < 4; mi++) {
                    ldsm_x4(ah[mi][0], ah[mi][1], ah[mi][2], ah[mi][3],
                            uAh + aoff + mi * (16 * RS4));
                    ldsm_x4(al[mi][0], al[mi][1], al[mi][2], al[mi][3],
                            uAl + aoff + mi * (16 * RS4));
                }
            }
            uint32_t bh[8], bl[8];
            {
                uint32_t brow = (uint32_t)(nbase + lr + ((g >> 1) << 3));
                uint32_t bkb  = (uint32_t)(s * 32 + ((g & 1) << 4));
                uint32_t boff = brow * RS4 + bkb;
                ldsm_x4(bh[0], bh[1], bh[2], bh[3], uBh + boff);
                ldsm_x4(bh[4], bh[5], bh[6], bh[7], uBh + boff + 16 * RS4);
                ldsm_x4(bl[0], bl[1], bl[2], bl[3], uBl + boff);
                ldsm_x4(bl[4], bl[5], bl[6], bl[7], uBl + boff + 16 * RS4);
            }
#pragma unroll
            for (int mi = 0; mi < 4; mi++) {
#pragma unroll
                for (int ni = 0; ni < 4; ni++) {
                    mma_bf16(acc[mi][ni], ah[mi], bh[ni * 2], bh[ni * 2 + 1]);
                    mma_bf16(acc[mi][ni], ah[mi], bl[ni * 2], bl[ni * 2 + 1]);
                    mma_bf16(acc[mi][ni], al[mi], bh[ni * 2], bh[ni * 2 + 1]);
                }
            }
        }
        __syncthreads();
    }

    const int gid = lane >> 2, tig = lane & 3;
    const int rowA = blockIdx.y * 128 + mbase + gid;
    const int colA = blockIdx.x * 128 + nbase + tig * 2;
#pragma unroll
    for (int mi = 0; mi < 4; mi++) {
#pragma unroll
        for (int ni = 0; ni < 4; ni++) {
            float* c0 = C + (size_t)(rowA + mi * 16) * Nn + colA + ni * 8;
            float* c1 = C + (size_t)(rowA + mi * 16 + 8) * Nn + colA + ni * 8;
            c0[0] = acc[mi][ni][0];
            c0[1] = acc[mi][ni][1];
            c1[0] = acc[mi][ni][2];
            c1[1] = acc[mi][ni][3];
        }
    }
}

// ---------------------------------------------------------------------------
// RoPE (in-place on g_q, g_k)
// ---------------------------------------------------------------------------
__global__ __launch_bounds__(256) void rope_kernel(float* __restrict__ q,
                                                   float* __restrict__ k) {
    int idx = blockIdx.x * blockDim.x + threadIdx.x;
    const int total = M_SZ * H_SZ * (HD_SZ / 2);
    if (idx >= total) return;

    int i = idx & 63;
    int h = (idx >> 6) & 15;
    int m = idx >> 10;
    int pos = m & (N_SZ - 1);

    float inv_freq = powf(10000.0f, -(float)i * (1.0f / 64.0f));
    float f = (float)pos * inv_freq;
    float s, c;
    sincosf(f, &s, &c);

    size_t base = (size_t)m * D_SZ + h * HD_SZ;
    float q1 = q[base + i], q2 = q[base + 64 + i];
    q[base + i]      = q1 * c - q2 * s;
    q[base + 64 + i] = q2 * c + q1 * s;

    float k1 = k[base + i], k2 = k[base + 64 + i];
    k[base + i]      = k1 * c - k2 * s;
    k[base + 64 + i] = k2 * c + k1 * s;
}

// ===========================================================================
// HMMA flash attention (unchanged from R7): fp32 q/k/v in, hi/lo bf16 O out.
// ===========================================================================
#define SROW   136
#define SROWB  272
#define AMAT   (128 * SROW)
#define ATT_SMEM (6 * AMAT * 2)

__global__ __launch_bounds__(256) void attn_hmma(
    const float* __restrict__ q, const float* __restrict__ k,
    const float* __restrict__ v,
    __nv_bfloat16* __restrict__ oh, __nv_bfloat16* __restrict__ ol) {
    extern __shared__ uint16_t sm[];
    uint16_t* Qh = sm;
    uint16_t* Ql = sm + AMAT;
    uint16_t* Kh = sm + 2 * AMAT;
    uint16_t* Kl = sm + 3 * AMAT;
    uint16_t* Vh = sm + 4 * AMAT;
    uint16_t* Vl = sm + 5 * AMAT;
    const uint32_t uQh = smem_u32(Qh), uQl = smem_u32(Ql);
    const uint32_t uKh = smem_u32(Kh), uKl = smem_u32(Kl);
    const uint32_t uVh = smem_u32(Vh), uVl = smem_u32(Vl);

    const int bh = blockIdx.y;
    const int b = bh >> 4, h = bh & 15;
    const int q0 = blockIdx.x * 128;
    const int tid = threadIdx.x;
    const int warp = tid >> 5, lane = tid & 31;
    const int g8 = lane >> 3, lr = lane & 7;
    const int g4 = lane >> 2, t4 = lane & 3;

    const float scale = 0.08838834764831845f;

    const float* qb = q + (size_t)(b * N_SZ + q0) * D_SZ + h * HD_SZ;
#pragma unroll
    for (int it = 0; it < 16; it++) {
        int e = tid + it * 256;
        int r = e >> 5, c4 = e & 31;
        float4 f = *(const float4*)(qb + (size_t)r * D_SZ + c4 * 4);
        f.x *= scale; f.y *= scale; f.z *= scale; f.w *= scale;
        uint2 hi, lo;
        split4(f, hi, lo);
        *(uint2*)((char*)Qh + r * SROWB + c4 * 8) = hi;
        *(uint2*)((char*)Ql + r * SROWB + c4 * 8) = lo;
    }

    float accO[16][4];
#pragma unroll
    for (int nd = 0; nd < 16; nd++)
#pragma unroll
        for (int e = 0; e < 4; e++) accO[nd][e] = 0.0f;
    float m0 = -1e30f, m1 = -1e30f, l0 = 0.0f, l1 = 0.0f;

    for (int kt = 0; kt < N_SZ / 128; kt++) {
        __syncthreads();
        const float* kb = k + (size_t)(b * N_SZ + kt * 128) * D_SZ + h * HD_SZ;
        const float* vb = v + (size_t)(b * N_SZ + kt * 128) * D_SZ + h * HD_SZ;
#pragma unroll
        for (int it = 0; it < 16; it++) {
            int e = tid + it * 256;
            int r = e >> 5, c4 = e & 31;
            uint2 hi, lo;
            float4 fk = *(const float4*)(kb + (size_t)r * D_SZ + c4 * 4);
            split4(fk, hi, lo);
            *(uint2*)((char*)Kh + r * SROWB + c4 * 8) = hi;
            *(uint2*)((char*)Kl + r * SROWB + c4 * 8) = lo;
            float4 fv = *(const float4*)(vb + (size_t)r * D_SZ + c4 * 4);
            split4(fv, hi, lo);
            *(uint2*)((char*)Vh + r * SROWB + c4 * 8) = hi;
            *(uint2*)((char*)Vl + r * SROWB + c4 * 8) = lo;
        }
        __syncthreads();

        float acc[16][4];
#pragma unroll
        for (int nt = 0; nt < 16; nt++)
#pragma unroll
            for (int e = 0; e < 4; e++) acc[nt][e] = 0.0f;

        {
            const uint32_t arow = (uint32_t)(warp * 16 + lr + ((g8 & 1) << 3));
            const uint32_t brow_g = (uint32_t)(lr + ((g8 >> 1) << 3));
#pragma unroll
            for (int ks = 0; ks < 8; ks++) {
                uint32_t acol = (uint32_t)(ks * 32 + ((g8 >> 1) << 4));
                uint32_t qh[4], ql[4];
                ldsm_x4(qh[0], qh[1], qh[2], qh[3], uQh + arow * SROWB + acol);
                ldsm_x4(ql[0], ql[1], ql[2], ql[3], uQl + arow * SROWB + acol);
                uint32_t bcol = (uint32_t)(ks * 32 + ((g8 & 1) << 4));
#pragma unroll
                for (int np = 0; np < 8; np++) {
                    uint32_t boff = (np * 16 + brow_g) * SROWB + bcol;
                    uint32_t kh[4], kl[4];
                    ldsm_x4(kh[0], kh[1], kh[2], kh[3], uKh + boff);
                    ldsm_x4(kl[0], kl[1], kl[2], kl[3], uKl + boff);
                    mma_bf16(acc[2 * np],     qh, kh[0], kh[1]);
                    mma_bf16(acc[2 * np + 1], qh, kh[2], kh[3]);
                    mma_bf16(acc[2 * np],     qh, kl[0], kl[1]);
                    mma_bf16(acc[2 * np + 1], qh, kl[2], kl[3]);
                    mma_bf16(acc[2 * np],     ql, kh[0], kh[1]);
                    mma_bf16(acc[2 * np + 1], ql, kh[2], kh[3]);
                }
            }
        }

        float mx0 = -1e30f, mx1 = -1e30f;
#pragma unroll
        for (int nt = 0; nt < 16; nt++) {
            mx0 = fmaxf(mx0, fmaxf(acc[nt][0], acc[nt][1]));
            mx1 = fmaxf(mx1, fmaxf(acc[nt][2], acc[nt][3]));
        }
        mx0 = fmaxf(mx0, __shfl_xor_sync(0xFFFFFFFFu, mx0, 1));
        mx0 = fmaxf(mx0, __shfl_xor_sync(0xFFFFFFFFu, mx0, 2));
        mx1 = fmaxf(mx1, __shfl_xor_sync(0xFFFFFFFFu, mx1, 1));
        mx1 = fmaxf(mx1, __shfl_xor_sync(0xFFFFFFFFu, mx1, 2));
        float mn0 = fmaxf(m0, mx0), mn1 = fmaxf(m1, mx1);
        float corr0 = exp2p((m0 - mn0) * LOG2E);
        float corr1 = exp2p((m1 - mn1) * LOG2E);
        m0 = mn0; m1 = mn1;

        float sum0 = 0.0f, sum1 = 0.0f;
#pragma unroll
        for (int nt = 0; nt < 16; nt++) {
            acc[nt][0] = exp2p((acc[nt][0] - mn0) * LOG2E);
            acc[nt][1] = exp2p((acc[nt][1] - mn0) * LOG2E);
            acc[nt][2] = exp2p((acc[nt][2] - mn1) * LOG2E);
            acc[nt][3] = exp2p((acc[nt][3] - mn1) * LOG2E);
            sum0 += acc[nt][0] + acc[nt][1];
            sum1 += acc[nt][2] + acc[nt][3];
        }
        sum0 += __shfl_xor_sync(0xFFFFFFFFu, sum0, 1);
        sum0 += __shfl_xor_sync(0xFFFFFFFFu, sum0, 2);
        sum1 += __shfl_xor_sync(0xFFFFFFFFu, sum1, 1);
        sum1 += __shfl_xor_sync(0xFFFFFFFFu, sum1, 2);
        l0 = l0 * corr0 + sum0;
        l1 = l1 * corr1 + sum1;

#pragma unroll
        for (int nd = 0; nd < 16; nd++) {
            accO[nd][0] *= corr0; accO[nd][1] *= corr0;
            accO[nd][2] *= corr1; accO[nd][3] *= corr1;
        }

        const uint32_t vrow_g = (uint32_t)(lr + ((g8 & 1) << 3));
        const uint32_t vcol_g = (uint32_t)((g8 >> 1) << 4);
#pragma unroll
        for (int kk = 0; kk < 8; kk++) {
            uint32_t pah[4], pal[4];
            {
                int n0 = 2 * kk, n1 = 2 * kk + 1;
                split2(acc[n0][0], acc[n0][1], pah[0], pal[0]);
                split2(acc[n0][2], acc[n0][3], pah[1], pal[1]);
                split2(acc[n1][0], acc[n1][1], pah[2], pal[2]);
                split2(acc[n1][2], acc[n1][3], pah[3], pal[3]);
            }
            uint32_t vbase_row = (uint32_t)(kk * 16) + vrow_g;
#pragma unroll
            for (int half = 0; half < 2; half++) {
                uint32_t vh[4][4], vl[4][4];
#pragma unroll
                for (int j = 0; j < 4; j++) {
                    uint32_t ndp = half * 4 + j;
                    uint32_t voff = vbase_row * SROWB + ndp * 32 + vcol_g;
                    ldsm_x4_t(vh[j][0], vh[j][1], vh[j][2], vh[j][3], uVh + voff);
                    ldsm_x4_t(vl[j][0], vl[j][1], vl[j][2], vl[j][3], uVl + voff);
                }
#pragma unroll
                for (int j = 0; j < 4; j++) {
                    int nda = (half * 4 + j) * 2, ndb = nda + 1;
                    mma_bf16(accO[nda], pah, vh[j][0], vh[j][1]);
                    mma_bf16(accO[ndb], pah, vh[j][2], vh[j][3]);
                    mma_bf16(accO[nda], pah, vl[j][0], vl[j][1]);
                    mma_bf16(accO[ndb], pah, vl[j][2], vl[j][3]);
                    mma_bf16(accO[nda], pal, vh[j][0], vh[j][1]);
                    mma_bf16(accO[ndb], pal, vh[j][2], vh[j][3]);
                }
            }
        }
    }

    float inv0 = 1.0f / l0, inv1 = 1.0f / l1;
    const size_t m_row0 = (size_t)(b * N_SZ + q0 + warp * 16 + g4);
    const size_t m_row1 = m_row0 + 8;
    const int colb = h * HD_SZ + t4 * 2;
#pragma unroll
    for (int nd = 0; nd < 16; nd++) {
        uint32_t hw, lw;
        split2(accO[nd][0] * inv0, accO[nd][1] * inv0, hw, lw);
        *(uint32_t*)(oh + m_row0 * D_SZ + colb + nd * 8) = hw;
        *(uint32_t*)(ol + m_row0 * D_SZ + colb + nd * 8) = lw;
        split2(accO[nd][2] * inv1, accO[nd][3] * inv1, hw, lw);
        *(uint32_t*)(oh + m_row1 * D_SZ + colb + nd * 8) = hw;
        *(uint32_t*)(ol + m_row1 * D_SZ + colb + nd * 8) = lw;
    }
}

// ---------------------------------------------------------------------------
// Launch
// ---------------------------------------------------------------------------
extern "C" void kernel_launch(void* const* d_in, const int* in_sizes, int n_in,
                              void* d_out, int out_size) {
    const float* x  = (const float*)d_in[0];
    const float* Wq = (const float*)d_in[1];
    const float* Wk = (const float*)d_in[2];
    const float* Wv = (const float*)d_in[3];
    const float* Wo = (const float*)d_in[4];
    float* out = (float*)d_out;

    float *q_ptr, *k_ptr, *v_ptr;
    __nv_bfloat16 *xh, *xl, *wh, *wl, *oh, *ol;
    cudaGetSymbolAddress((void**)&q_ptr, g_q);
    cudaGetSymbolAddress((void**)&k_ptr, g_k);
    cudaGetSymbolAddress((void**)&v_ptr, g_v);
    cudaGetSymbolAddress((void**)&xh, g_xh);
    cudaGetSymbolAddress((void**)&xl, g_xl);
    cudaGetSymbolAddress((void**)&wh, g_wh);
    cudaGetSymbolAddress((void**)&wl, g_wl);
    cudaGetSymbolAddress((void**)&oh, g_oh);
    cudaGetSymbolAddress((void**)&ol, g_ol);

    cudaFuncSetAttribute(gemm4, cudaFuncAttributeMaxDynamicSharedMemorySize,
                         G4_SMEM);
    cudaFuncSetAttribute(attn_hmma, cudaFuncAttributeMaxDynamicSharedMemorySize,
                         ATT_SMEM);

    const int nx4 = M_SZ * D_SZ / 4;
    const int nw4 = D_SZ * D_SZ / 4;
    const size_t woff = (size_t)D_SZ * D_SZ;

    // Pre-split activations and all four weights
    split_kernel<<<nx4 / 256, 256>>>((const float4*)x, (uint2*)xh, (uint2*)xl, nx4);
    split_kernel<<<nw4 / 256, 256>>>((const float4*)Wq, (uint2*)wh, (uint2*)wl, nw4);
    split_kernel<<<nw4 / 256, 256>>>((const float4*)Wk,
                                     (uint2*)(wh + woff), (uint2*)(wl + woff), nw4);
    split_kernel<<<nw4 / 256, 256>>>((const float4*)Wv,
                                     (uint2*)(wh + 2 * woff), (uint2*)(wl + 2 * woff), nw4);
    split_kernel<<<nw4 / 256, 256>>>((const float4*)Wo,
                                     (uint2*)(wh + 3 * woff), (uint2*)(wl + 3 * woff), nw4);

    // Fused Q/K/V projection: gridDim.z picks weight slice + destination
    dim3 gq(D_SZ / 128, M_SZ / 128, 3);    // (16, 32, 3)
    gemm4<<<gq, 256, G4_SMEM>>>(xh, xl, wh, wl, q_ptr, k_ptr, v_ptr, D_SZ, D_SZ);

    int rope_total = M_SZ * H_SZ * (HD_SZ / 2);
    rope_kernel<<<(rope_total + 255) / 256, 256>>>(q_ptr, k_ptr);

    dim3 ga(N_SZ / 128, B_SZ * H_SZ);      // (16, 32)
    attn_hmma<<<ga, 256, ATT_SMEM>>>(q_ptr, k_ptr, v_ptr, oh, ol);

    // O projection
    dim3 go(D_SZ / 128, M_SZ / 128, 1);
    gemm4<<<go, 256, G4_SMEM>>>(oh, ol, wh + 3 * woff, wl + 3 * woff,
                                out, out, out, D_SZ, D_SZ);
}

// round 9
// speedup vs baseline: 4.0227x; 1.1786x over previous
#include <cuda_runtime.h>
#include <cuda_bf16.h>
#include <cstdint>

#define B_SZ 2
#define N_SZ 2048
#define D_SZ 2048
#define H_SZ 16
#define HD_SZ 128
#define M_SZ (B_SZ * N_SZ)   // 4096

// Tiled operand layout: 16KB blocks [128 rows x 64 cols bf16], row stride
// 128 B, 16B-group swizzle c8 ^= (r & 7). Block id = panel*32 + kchunk.
#define TB 16384

// Scratch (static device arrays; no allocation allowed)
__device__ float g_q[M_SZ * D_SZ];
__device__ float g_k[M_SZ * D_SZ];
__device__ float g_v[M_SZ * D_SZ];
__device__ __align__(128) __nv_bfloat16 g_xh[M_SZ * D_SZ];
__device__ __align__(128) __nv_bfloat16 g_xl[M_SZ * D_SZ];
__device__ __align__(128) __nv_bfloat16 g_wh[4 * D_SZ * D_SZ];
__device__ __align__(128) __nv_bfloat16 g_wl[4 * D_SZ * D_SZ];
__device__ __align__(128) __nv_bfloat16 g_oh[M_SZ * D_SZ];
__device__ __align__(128) __nv_bfloat16 g_ol[M_SZ * D_SZ];

// ===========================================================================
// PTX helpers (sm_80/sm_90 base-arch: legal at compute_103)
// ===========================================================================
__device__ __forceinline__ uint32_t smem_u32(const void* p) {
    uint32_t a;
    asm("{ .reg .u64 t; cvta.to.shared.u64 t, %1; cvt.u32.u64 %0, t; }"
        : "=r"(a) : "l"(p));
    return a;
}

__device__ __forceinline__ void ldsm_x4(uint32_t& r0, uint32_t& r1,
                                        uint32_t& r2, uint32_t& r3,
                                        uint32_t addr) {
    asm volatile("ldmatrix.sync.aligned.m8n8.x4.shared.b16 {%0,%1,%2,%3}, [%4];"
                 : "=r"(r0), "=r"(r1), "=r"(r2), "=r"(r3) : "r"(addr));
}

__device__ __forceinline__ void ldsm_x4_t(uint32_t& r0, uint32_t& r1,
                                          uint32_t& r2, uint32_t& r3,
                                          uint32_t addr) {
    asm volatile("ldmatrix.sync.aligned.m8n8.x4.trans.shared.b16 {%0,%1,%2,%3}, [%4];"
                 : "=r"(r0), "=r"(r1), "=r"(r2), "=r"(r3) : "r"(addr));
}

__device__ __forceinline__ void mma_bf16(float* d, const uint32_t* a,
                                         uint32_t b0, uint32_t b1) {
    asm volatile(
        "mma.sync.aligned.m16n8k16.row.col.f32.bf16.bf16.f32 "
        "{%0,%1,%2,%3}, {%4,%5,%6,%7}, {%8,%9}, {%0,%1,%2,%3};"
        : "+f"(d[0]), "+f"(d[1]), "+f"(d[2]), "+f"(d[3])
        : "r"(a[0]), "r"(a[1]), "r"(a[2]), "r"(a[3]), "r"(b0), "r"(b1));
}

// Non-tensor bulk TMA: contiguous global -> contiguous shared
#define CP_BULK(saddr, gptr, bytes, mbar) \
    asm volatile( \
        "cp.async.bulk.shared::cta.global.mbarrier::complete_tx::bytes " \
        "[%0], [%1], %2, [%3];" \
        :: "r"(saddr), "l"(gptr), "r"(bytes), "r"(mbar) : "memory")

#define MBARRIER_INIT(mbar, count) \
    asm volatile("mbarrier.init.shared.b64 [%0], %1;" \
                 :: "r"(mbar), "r"((uint32_t)(count)) : "memory")

#define MBARRIER_EXPECT_TX(mbar, bytes) \
    asm volatile("mbarrier.arrive.expect_tx.shared.b64 _, [%0], %1;" \
                 :: "r"(mbar), "r"((uint32_t)(bytes)) : "memory")

#define MBARRIER_WAIT_PARITY(mbar, parity) do { \
    uint32_t _mb = (mbar); \
    uint32_t _ph = (parity); \
    asm volatile( \
        "{\n\t" \
        ".reg .pred P1;\n\t" \
        "WAIT_LOOP_%=:\n\t" \
        "mbarrier.try_wait.parity.acquire.cta.shared::cta.b64 P1, [%0], %1, 0x989680;\n\t" \
        "@P1 bra.uni WAIT_DONE_%=;\n\t" \
        "bra.uni WAIT_LOOP_%=;\n\t" \
        "WAIT_DONE_%=:\n\t" \
        "}" \
        :: "r"(_mb), "r"(_ph) : "memory"); \
} while (0)

#define FENCE_PROXY_ASYNC() \
    asm volatile("fence.proxy.async.shared::cta;" ::: "memory")

// pack two fp32 -> bf16x2 (e0 low, e1 high)
__device__ __forceinline__ uint32_t packbf(float e0, float e1) {
    uint32_t r;
    asm("cvt.rn.bf16x2.f32 %0, %1, %2;" : "=r"(r) : "f"(e1), "f"(e0));
    return r;
}

// Split fp32x4 -> hi/lo bf16x2 pairs
__device__ __forceinline__ void split4(float4 f, uint2& hi, uint2& lo) {
    hi.x = packbf(f.x, f.y);
    hi.y = packbf(f.z, f.w);
    float h0 = __int_as_float(hi.x << 16);
    float h1 = __int_as_float(hi.x & 0xFFFF0000u);
    float h2 = __int_as_float(hi.y << 16);
    float h3 = __int_as_float(hi.y & 0xFFFF0000u);
    lo.x = packbf(f.x - h0, f.y - h1);
    lo.y = packbf(f.z - h2, f.w - h3);
}

// split two fp32 to hi/lo bf16x2 words
__device__ __forceinline__ void split2(float e0, float e1,
                                       uint32_t& h, uint32_t& l) {
    h = packbf(e0, e1);
    float h0 = __int_as_float(h << 16);
    float h1 = __int_as_float(h & 0xFFFF0000u);
    l = packbf(e0 - h0, e1 - h1);
}

// Fast exp2 on the FMA pipe
__device__ __forceinline__ float exp2p(float y) {
    y = fmaxf(y, -126.0f);
    int n = __float2int_rd(y);
    float f = y - (float)n;
    float r = 1.8775767e-3f;
    r = fmaf(r, f, 8.9893397e-3f);
    r = fmaf(r, f, 5.5826318e-2f);
    r = fmaf(r, f, 2.4015361e-1f);
    r = fmaf(r, f, 6.9315308e-1f);
    r = fmaf(r, f, 1.0f);
    return r * __int_as_float((n + 127) << 23);
}

#define LOG2E 1.4426950408889634f

// ===========================================================================
// Split + tile transform: fp32 [nrows x 2048] -> tiled/swizzled hi/lo bf16.
// Thread handles one 16B out-group (8 elems).
// ===========================================================================
__global__ __launch_bounds__(256) void split_tiled(
    const float* __restrict__ src, __nv_bfloat16* __restrict__ hi,
    __nv_bfloat16* __restrict__ lo, int nrows) {
    int idx = blockIdx.x * 256 + threadIdx.x;
    if (idx >= nrows * 256) return;
    int rg = idx >> 8;            // global row
    int g = idx & 255;            // 16B group in row
    int kc = g >> 3, c8 = g & 7;
    int panel = rg >> 7, r = rg & 127;

    const float4* s = (const float4*)(src + (size_t)rg * 2048 + kc * 64 + c8 * 8);
    float4 f0 = s[0], f1 = s[1];
    uint2 h0, l0, h1, l1;
    split4(f0, h0, l0);
    split4(f1, h1, l1);

    size_t off = (size_t)(panel * 32 + kc) * TB
               + (uint32_t)(r * 128 + ((c8 ^ (r & 7)) << 4));
    *(uint4*)((char*)hi + off) = make_uint4(h0.x, h0.y, h1.x, h1.y);
    *(uint4*)((char*)lo + off) = make_uint4(l0.x, l0.y, l1.x, l1.y);
}

// ===========================================================================
// gemm5: C[M,Nn] = A @ W^T, tiled/swizzled bf16 hi/lo inputs via
// cp.async.bulk 2-stage mbarrier pipeline. CTA tile 128x128, BK=64, 256 thr.
// ===========================================================================
#define STB   (4 * TB)            // bytes per stage (Ah, Al, Bh, Bl)
#define G5_MBAR (2 * STB)         // mbar offsets: +0, +8
#define G5_SMEM (2 * STB + 32)

__global__ __launch_bounds__(256) void gemm5(
    const __nv_bfloat16* __restrict__ Ah, const __nv_bfloat16* __restrict__ Al,
    const __nv_bfloat16* __restrict__ Wh, const __nv_bfloat16* __restrict__ Wl,
    float* __restrict__ C0, float* __restrict__ C1, float* __restrict__ C2,
    int Nn) {
    extern __shared__ char dsm[];
    const uint32_t sb = smem_u32(dsm);

    const int tid = threadIdx.x;
    const int warp = tid >> 5;
    const int lane = tid & 31;
    const int mbase = (warp >> 2) * 64;
    const int nbase = (warp & 3) * 32;

    const int z = blockIdx.z;
    float* C = (z == 0) ? C0 : (z == 1) ? C1 : C2;
    const char* pAh = (const char*)Ah;
    const char* pAl = (const char*)Al;
    const char* pBh = (const char*)(Wh + (size_t)z * D_SZ * D_SZ);
    const char* pBl = (const char*)(Wl + (size_t)z * D_SZ * D_SZ);

    float acc[4][4][4];
#pragma unroll
    for (int i = 0; i < 4; i++)
#pragma unroll
        for (int j = 0; j < 4; j++)
#pragma unroll
            for (int e = 0; e < 4; e++) acc[i][j][e] = 0.0f;

    const uint32_t mb0 = sb + G5_MBAR;

    if (tid == 0) {
        MBARRIER_INIT(mb0, 1);
        MBARRIER_INIT(mb0 + 8, 1);
    }
    __syncthreads();

    auto issue = [&](int st, int kc) {
        uint32_t s0 = sb + st * STB;
        uint32_t mb = mb0 + st * 8;
        size_t offA = (size_t)(blockIdx.y * 32 + kc) * TB;
        size_t offB = (size_t)(blockIdx.x * 32 + kc) * TB;
        MBARRIER_EXPECT_TX(mb, 4 * TB);
        CP_BULK(s0,          pAh + offA, TB, mb);
        CP_BULK(s0 + TB,     pAl + offA, TB, mb);
        CP_BULK(s0 + 2 * TB, pBh + offB, TB, mb);
        CP_BULK(s0 + 3 * TB, pBl + offB, TB, mb);
    };

    if (tid == 0) {
        issue(0, 0);
        issue(1, 1);
    }

    const int g = lane >> 3, lr = lane & 7;
    const uint32_t arow = (uint32_t)(mbase + lr + ((g & 1) << 3));
    const uint32_t brow = (uint32_t)(nbase + lr + ((g >> 1) << 3));
    const uint32_t aswz = arow & 7, bswz = brow & 7;

    for (int kc = 0; kc < 32; kc++) {
        const int st = kc & 1;
        MBARRIER_WAIT_PARITY(mb0 + st * 8, (kc >> 1) & 1);

        const uint32_t uAh = sb + st * STB;
        const uint32_t uAl = uAh + TB;
        const uint32_t uBh = uAh + 2 * TB;
        const uint32_t uBl = uAh + 3 * TB;

#pragma unroll
        for (int s = 0; s < 4; s++) {
            uint32_t c8a = (uint32_t)(s * 2 + (g >> 1));
            uint32_t c8b = (uint32_t)(s * 2 + (g & 1));
            uint32_t aoff = arow * 128 + ((c8a ^ aswz) << 4);
            uint32_t boff = brow * 128 + ((c8b ^ bswz) << 4);

            uint32_t ah[4][4], al[4][4];
#pragma unroll
            for (int mi = 0; mi < 4; mi++) {
                ldsm_x4(ah[mi][0], ah[mi][1], ah[mi][2], ah[mi][3],
                        uAh + aoff + mi * 2048);
                ldsm_x4(al[mi][0], al[mi][1], al[mi][2], al[mi][3],
                        uAl + aoff + mi * 2048);
            }
            uint32_t bh[8], bl[8];
            ldsm_x4(bh[0], bh[1], bh[2], bh[3], uBh + boff);
            ldsm_x4(bh[4], bh[5], bh[6], bh[7], uBh + boff + 2048);
            ldsm_x4(bl[0], bl[1], bl[2], bl[3], uBl + boff);
            ldsm_x4(bl[4], bl[5], bl[6], bl[7], uBl + boff + 2048);

#pragma unroll
            for (int mi = 0; mi < 4; mi++) {
#pragma unroll
                for (int ni = 0; ni < 4; ni++) {
                    mma_bf16(acc[mi][ni], ah[mi], bh[ni * 2], bh[ni * 2 + 1]);
                    mma_bf16(acc[mi][ni], ah[mi], bl[ni * 2], bl[ni * 2 + 1]);
                    mma_bf16(acc[mi][ni], al[mi], bh[ni * 2], bh[ni * 2 + 1]);
                }
            }
        }
        __syncthreads();
        if (kc + 2 < 32 && tid == 0) {
            FENCE_PROXY_ASYNC();
            issue(st, kc + 2);
        }
    }

    const int gid = lane >> 2, tig = lane & 3;
    const int rowA = blockIdx.y * 128 + mbase + gid;
    const int colA = blockIdx.x * 128 + nbase + tig * 2;
#pragma unroll
    for (int mi = 0; mi < 4; mi++) {
#pragma unroll
        for (int ni = 0; ni < 4; ni++) {
            float* c0 = C + (size_t)(rowA + mi * 16) * Nn + colA + ni * 8;
            float* c1 = C + (size_t)(rowA + mi * 16 + 8) * Nn + colA + ni * 8;
            c0[0] = acc[mi][ni][0];
            c0[1] = acc[mi][ni][1];
            c1[0] = acc[mi][ni][2];
            c1[1] = acc[mi][ni][3];
        }
    }
}

// ---------------------------------------------------------------------------
// RoPE (in-place on g_q, g_k)
// ---------------------------------------------------------------------------
__global__ __launch_bounds__(256) void rope_kernel(float* __restrict__ q,
                                                   float* __restrict__ k) {
    int idx = blockIdx.x * blockDim.x + threadIdx.x;
    const int total = M_SZ * H_SZ * (HD_SZ / 2);
    if (idx >= total) return;

    int i = idx & 63;
    int h = (idx >> 6) & 15;
    int m = idx >> 10;
    int pos = m & (N_SZ - 1);

    float inv_freq = powf(10000.0f, -(float)i * (1.0f / 64.0f));
    float f = (float)pos * inv_freq;
    float s, c;
    sincosf(f, &s, &c);

    size_t base = (size_t)m * D_SZ + h * HD_SZ;
    float q1 = q[base + i], q2 = q[base + 64 + i];
    q[base + i]      = q1 * c - q2 * s;
    q[base + 64 + i] = q2 * c + q1 * s;

    float k1 = k[base + i], k2 = k[base + 64 + i];
    k[base + i]      = k1 * c - k2 * s;
    k[base + 64 + i] = k2 * c + k1 * s;
}

// ===========================================================================
// HMMA flash attention: fp32 q/k/v in, TILED hi/lo bf16 O out.
// ===========================================================================
#define SROW   136
#define SROWB  272
#define AMAT   (128 * SROW)
#define ATT_SMEM (6 * AMAT * 2)

__global__ __launch_bounds__(256) void attn_hmma(
    const float* __restrict__ q, const float* __restrict__ k,
    const float* __restrict__ v,
    __nv_bfloat16* __restrict__ oh, __nv_bfloat16* __restrict__ ol) {
    extern __shared__ uint16_t sm[];
    uint16_t* Qh = sm;
    uint16_t* Ql = sm + AMAT;
    uint16_t* Kh = sm + 2 * AMAT;
    uint16_t* Kl = sm + 3 * AMAT;
    uint16_t* Vh = sm + 4 * AMAT;
    uint16_t* Vl = sm + 5 * AMAT;
    const uint32_t uQh = smem_u32(Qh), uQl = smem_u32(Ql);
    const uint32_t uKh = smem_u32(Kh), uKl = smem_u32(Kl);
    const uint32_t uVh = smem_u32(Vh), uVl = smem_u32(Vl);

    const int bh = blockIdx.y;
    const int b = bh >> 4, h = bh & 15;
    const int q0 = blockIdx.x * 128;
    const int tid = threadIdx.x;
    const int warp = tid >> 5, lane = tid & 31;
    const int g8 = lane >> 3, lr = lane & 7;
    const int g4 = lane >> 2, t4 = lane & 3;

    const float scale = 0.08838834764831845f;

    const float* qb = q + (size_t)(b * N_SZ + q0) * D_SZ + h * HD_SZ;
#pragma unroll
    for (int it = 0; it < 16; it++) {
        int e = tid + it * 256;
        int r = e >> 5, c4 = e & 31;
        float4 f = *(const float4*)(qb + (size_t)r * D_SZ + c4 * 4);
        f.x *= scale; f.y *= scale; f.z *= scale; f.w *= scale;
        uint2 hi, lo;
        split4(f, hi, lo);
        *(uint2*)((char*)Qh + r * SROWB + c4 * 8) = hi;
        *(uint2*)((char*)Ql + r * SROWB + c4 * 8) = lo;
    }

    float accO[16][4];
#pragma unroll
    for (int nd = 0; nd < 16; nd++)
#pragma unroll
        for (int e = 0; e < 4; e++) accO[nd][e] = 0.0f;
    float m0 = -1e30f, m1 = -1e30f, l0 = 0.0f, l1 = 0.0f;

    for (int kt = 0; kt < N_SZ / 128; kt++) {
        __syncthreads();
        const float* kb = k + (size_t)(b * N_SZ + kt * 128) * D_SZ + h * HD_SZ;
        const float* vb = v + (size_t)(b * N_SZ + kt * 128) * D_SZ + h * HD_SZ;
#pragma unroll
        for (int it = 0; it < 16; it++) {
            int e = tid + it * 256;
            int r = e >> 5, c4 = e & 31;
            uint2 hi, lo;
            float4 fk = *(const float4*)(kb + (size_t)r * D_SZ + c4 * 4);
            split4(fk, hi, lo);
            *(uint2*)((char*)Kh + r * SROWB + c4 * 8) = hi;
            *(uint2*)((char*)Kl + r * SROWB + c4 * 8) = lo;
            float4 fv = *(const float4*)(vb + (size_t)r * D_SZ + c4 * 4);
            split4(fv, hi, lo);
            *(uint2*)((char*)Vh + r * SROWB + c4 * 8) = hi;
            *(uint2*)((char*)Vl + r * SROWB + c4 * 8) = lo;
        }
        __syncthreads();

        float acc[16][4];
#pragma unroll
        for (int nt = 0; nt < 16; nt++)
#pragma unroll
            for (int e = 0; e < 4; e++) acc[nt][e] = 0.0f;

        {
            const uint32_t arow = (uint32_t)(warp * 16 + lr + ((g8 & 1) << 3));
            const uint32_t brow_g = (uint32_t)(lr + ((g8 >> 1) << 3));
#pragma unroll
            for (int ks = 0; ks < 8; ks++) {
                uint32_t acol = (uint32_t)(ks * 32 + ((g8 >> 1) << 4));
                uint32_t qh[4], ql[4];
                ldsm_x4(qh[0], qh[1], qh[2], qh[3], uQh + arow * SROWB + acol);
                ldsm_x4(ql[0], ql[1], ql[2], ql[3], uQl + arow * SROWB + acol);
                uint32_t bcol = (uint32_t)(ks * 32 + ((g8 & 1) << 4));
#pragma unroll
                for (int np = 0; np < 8; np++) {
                    uint32_t boff = (np * 16 + brow_g) * SROWB + bcol;
                    uint32_t kh[4], kl[4];
                    ldsm_x4(kh[0], kh[1], kh[2], kh[3], uKh + boff);
                    ldsm_x4(kl[0], kl[1], kl[2], kl[3], uKl + boff);
                    mma_bf16(acc[2 * np],     qh, kh[0], kh[1]);
                    mma_bf16(acc[2 * np + 1], qh, kh[2], kh[3]);
                    mma_bf16(acc[2 * np],     qh, kl[0], kl[1]);
                    mma_bf16(acc[2 * np + 1], qh, kl[2], kl[3]);
                    mma_bf16(acc[2 * np],     ql, kh[0], kh[1]);
                    mma_bf16(acc[2 * np + 1], ql, kh[2], kh[3]);
                }
            }
        }

        float mx0 = -1e30f, mx1 = -1e30f;
#pragma unroll
        for (int nt = 0; nt < 16; nt++) {
            mx0 = fmaxf(mx0, fmaxf(acc[nt][0], acc[nt][1]));
            mx1 = fmaxf(mx1, fmaxf(acc[nt][2], acc[nt][3]));
        }
        mx0 = fmaxf(mx0, __shfl_xor_sync(0xFFFFFFFFu, mx0, 1));
        mx0 = fmaxf(mx0, __shfl_xor_sync(0xFFFFFFFFu, mx0, 2));
        mx1 = fmaxf(mx1, __shfl_xor_sync(0xFFFFFFFFu, mx1, 1));
        mx1 = fmaxf(mx1, __shfl_xor_sync(0xFFFFFFFFu, mx1, 2));
        float mn0 = fmaxf(m0, mx0), mn1 = fmaxf(m1, mx1);
        float corr0 = exp2p((m0 - mn0) * LOG2E);
        float corr1 = exp2p((m1 - mn1) * LOG2E);
        m0 = mn0; m1 = mn1;

        float sum0 = 0.0f, sum1 = 0.0f;
#pragma unroll
        for (int nt = 0; nt < 16; nt++) {
            acc[nt][0] = exp2p((acc[nt][0] - mn0) * LOG2E);
            acc[nt][1] = exp2p((acc[nt][1] - mn0) * LOG2E);
            acc[nt][2] = exp2p((acc[nt][2] - mn1) * LOG2E);
            acc[nt][3] = exp2p((acc[nt][3] - mn1) * LOG2E);
            sum0 += acc[nt][0] + acc[nt][1];
            sum1 += acc[nt][2] + acc[nt][3];
        }
        sum0 += __shfl_xor_sync(0xFFFFFFFFu, sum0, 1);
        sum0 += __shfl_xor_sync(0xFFFFFFFFu, sum0, 2);
        sum1 += __shfl_xor_sync(0xFFFFFFFFu, sum1, 1);
        sum1 += __shfl_xor_sync(0xFFFFFFFFu, sum1, 2);
        l0 = l0 * corr0 + sum0;
        l1 = l1 * corr1 + sum1;

#pragma unroll
        for (int nd = 0; nd < 16; nd++) {
            accO[nd][0] *= corr0; accO[nd][1] *= corr0;
            accO[nd][2] *= corr1; accO[nd][3] *= corr1;
        }

        const uint32_t vrow_g = (uint32_t)(lr + ((g8 & 1) << 3));
        const uint32_t vcol_g = (uint32_t)((g8 >> 1) << 4);
#pragma unroll
        for (int kk = 0; kk < 8; kk++) {
            uint32_t pah[4], pal[4];
            {
                int n0 = 2 * kk, n1 = 2 * kk + 1;
                split2(acc[n0][0], acc[n0][1], pah[0], pal[0]);
                split2(acc[n0][2], acc[n0][3], pah[1], pal[1]);
                split2(acc[n1][0], acc[n1][1], pah[2], pal[2]);
                split2(acc[n1][2], acc[n1][3], pah[3], pal[3]);
            }
            uint32_t vbase_row = (uint32_t)(kk * 16) + vrow_g;
#pragma unroll
            for (int half = 0; half < 2; half++) {
                uint32_t vh[4][4], vl[4][4];
#pragma unroll
                for (int j = 0; j < 4; j++) {
                    uint32_t ndp = half * 4 + j;
                    uint32_t voff = vbase_row * SROWB + ndp * 32 + vcol_g;
                    ldsm_x4_t(vh[j][0], vh[j][1], vh[j][2], vh[j][3], uVh + voff);
                    ldsm_x4_t(vl[j][0], vl[j][1], vl[j][2], vl[j][3], uVl + voff);
                }
#pragma unroll
                for (int j = 0; j < 4; j++) {
                    int nda = (half * 4 + j) * 2, ndb = nda + 1;
                    mma_bf16(accO[nda], pah, vh[j][0], vh[j][1]);
                    mma_bf16(accO[ndb], pah, vh[j][2], vh[j][3]);
                    mma_bf16(accO[nda], pah, vl[j][0], vl[j][1]);
                    mma_bf16(accO[ndb], pah, vl[j][2], vl[j][3]);
                    mma_bf16(accO[nda], pal, vh[j][0], vh[j][1]);
                    mma_bf16(accO[ndb], pal, vh[j][2], vh[j][3]);
                }
            }
        }
    }

    // ---- Epilogue: normalize, split, write TILED hi/lo layout ----
    float inv0 = 1.0f / l0, inv1 = 1.0f / l1;
    const int mrow0 = b * N_SZ + q0 + warp * 16 + g4;   // row1 = +8
    const int panel = mrow0 >> 7;
    const int r0 = mrow0 & 127;
    const uint32_t rsw = (uint32_t)(r0 & 7);            // same for r0+8
#pragma unroll
    for (int nd = 0; nd < 16; nd++) {
        int kchunk = h * 2 + (nd >> 3);
        uint32_t c8 = (uint32_t)(nd & 7);
        size_t blk = (size_t)(panel * 32 + kchunk) * TB;
        uint32_t in0 = (uint32_t)(r0 * 128) + ((c8 ^ rsw) << 4) + t4 * 4;
        uint32_t hw, lw;
        split2(accO[nd][0] * inv0, accO[nd][1] * inv0, hw, lw);
        *(uint32_t*)((char*)oh + blk + in0) = hw;
        *(uint32_t*)((char*)ol + blk + in0) = lw;
        split2(accO[nd][2] * inv1, accO[nd][3] * inv1, hw, lw);
        *(uint32_t*)((char*)oh + blk + in0 + 1024) = hw;
        *(uint32_t*)((char*)ol + blk + in0 + 1024) = lw;
    }
}

// ---------------------------------------------------------------------------
// Launch
// ---------------------------------------------------------------------------
extern "C" void kernel_launch(void* const* d_in, const int* in_sizes, int n_in,
                              void* d_out, int out_size) {
    const float* x  = (const float*)d_in[0];
    const float* Wq = (const float*)d_in[1];
    const float* Wk = (const float*)d_in[2];
    const float* Wv = (const float*)d_in[3];
    const float* Wo = (const float*)d_in[4];
    float* out = (float*)d_out;

    float *q_ptr, *k_ptr, *v_ptr;
    __nv_bfloat16 *xh, *xl, *wh, *wl, *oh, *ol;
    cudaGetSymbolAddress((void**)&q_ptr, g_q);
    cudaGetSymbolAddress((void**)&k_ptr, g_k);
    cudaGetSymbolAddress((void**)&v_ptr, g_v);
    cudaGetSymbolAddress((void**)&xh, g_xh);
    cudaGetSymbolAddress((void**)&xl, g_xl);
    cudaGetSymbolAddress((void**)&wh, g_wh);
    cudaGetSymbolAddress((void**)&wl, g_wl);
    cudaGetSymbolAddress((void**)&oh, g_oh);
    cudaGetSymbolAddress((void**)&ol, g_ol);

    cudaFuncSetAttribute(gemm5, cudaFuncAttributeMaxDynamicSharedMemorySize,
                         G5_SMEM);
    cudaFuncSetAttribute(attn_hmma, cudaFuncAttributeMaxDynamicSharedMemorySize,
                         ATT_SMEM);

    const size_t woff = (size_t)D_SZ * D_SZ;

    // Pre-split + tile all operands
    split_tiled<<<M_SZ, 256>>>(x, xh, xl, M_SZ);
    split_tiled<<<D_SZ, 256>>>(Wq, wh, wl, D_SZ);
    split_tiled<<<D_SZ, 256>>>(Wk, wh + woff, wl + woff, D_SZ);
    split_tiled<<<D_SZ, 256>>>(Wv, wh + 2 * woff, wl + 2 * woff, D_SZ);
    split_tiled<<<D_SZ, 256>>>(Wo, wh + 3 * woff, wl + 3 * woff, D_SZ);

    // Fused Q/K/V projection
    dim3 gq(D_SZ / 128, M_SZ / 128, 3);    // (16, 32, 3)
    gemm5<<<gq, 256, G5_SMEM>>>(xh, xl, wh, wl, q_ptr, k_ptr, v_ptr, D_SZ);

    int rope_total = M_SZ * H_SZ * (HD_SZ / 2);
    rope_kernel<<<(rope_total + 255) / 256, 256>>>(q_ptr, k_ptr);

    dim3 ga(N_SZ / 128, B_SZ * H_SZ);      // (16, 32)
    attn_hmma<<<ga, 256, ATT_SMEM>>>(q_ptr, k_ptr, v_ptr, oh, ol);

    // O projection (z=0 -> weight slice 3 passed as base)
    dim3 go(D_SZ / 128, M_SZ / 128, 1);
    gemm5<<<go, 256, G5_SMEM>>>(oh, ol, wh + 3 * woff, wl + 3 * woff,
                                out, out, out, D_SZ);
}

// round 10
// speedup vs baseline: 5.3978x; 1.3418x over previous
#include <cuda_runtime.h>
#include <cuda_fp16.h>
#include <cstdint>

#define B_SZ 2
#define N_SZ 2048
#define D_SZ 2048
#define H_SZ 16
#define HD_SZ 128
#define M_SZ (B_SZ * N_SZ)   // 4096

// Tiled operand layout: 16KB blocks [128 rows x 64 cols f16], row stride
// 128 B, 16B-group swizzle c8 ^= (r & 7). Block id = panel*32 + kchunk.
#define TB 16384

// Scratch (static device arrays; no allocation allowed)
__device__ float g_q[M_SZ * D_SZ];
__device__ float g_k[M_SZ * D_SZ];
__device__ float g_v[M_SZ * D_SZ];
__device__ __align__(128) __half g_xh[M_SZ * D_SZ];
__device__ __align__(128) __half g_xl[M_SZ * D_SZ];
__device__ __align__(128) __half g_wh[4 * D_SZ * D_SZ];
__device__ __align__(128) __half g_oh[M_SZ * D_SZ];
__device__ __align__(128) __half g_ol[M_SZ * D_SZ];

// ===========================================================================
// PTX helpers (sm_80/sm_90 base-arch: legal at compute_103)
// ===========================================================================
__device__ __forceinline__ uint32_t smem_u32(const void* p) {
    uint32_t a;
    asm("{ .reg .u64 t; cvta.to.shared.u64 t, %1; cvt.u32.u64 %0, t; }"
        : "=r"(a) : "l"(p));
    return a;
}

__device__ __forceinline__ void ldsm_x4(uint32_t& r0, uint32_t& r1,
                                        uint32_t& r2, uint32_t& r3,
                                        uint32_t addr) {
    asm volatile("ldmatrix.sync.aligned.m8n8.x4.shared.b16 {%0,%1,%2,%3}, [%4];"
                 : "=r"(r0), "=r"(r1), "=r"(r2), "=r"(r3) : "r"(addr));
}

__device__ __forceinline__ void ldsm_x4_t(uint32_t& r0, uint32_t& r1,
                                          uint32_t& r2, uint32_t& r3,
                                          uint32_t addr) {
    asm volatile("ldmatrix.sync.aligned.m8n8.x4.trans.shared.b16 {%0,%1,%2,%3}, [%4];"
                 : "=r"(r0), "=r"(r1), "=r"(r2), "=r"(r3) : "r"(addr));
}

__device__ __forceinline__ void mma_f16(float* d, const uint32_t* a,
                                        uint32_t b0, uint32_t b1) {
    asm volatile(
        "mma.sync.aligned.m16n8k16.row.col.f32.f16.f16.f32 "
        "{%0,%1,%2,%3}, {%4,%5,%6,%7}, {%8,%9}, {%0,%1,%2,%3};"
        : "+f"(d[0]), "+f"(d[1]), "+f"(d[2]), "+f"(d[3])
        : "r"(a[0]), "r"(a[1]), "r"(a[2]), "r"(a[3]), "r"(b0), "r"(b1));
}

// Non-tensor bulk TMA: contiguous global -> contiguous shared
#define CP_BULK(saddr, gptr, bytes, mbar) \
    asm volatile( \
        "cp.async.bulk.shared::cta.global.mbarrier::complete_tx::bytes " \
        "[%0], [%1], %2, [%3];" \
        :: "r"(saddr), "l"(gptr), "r"(bytes), "r"(mbar) : "memory")

#define MBARRIER_INIT(mbar, count) \
    asm volatile("mbarrier.init.shared.b64 [%0], %1;" \
                 :: "r"(mbar), "r"((uint32_t)(count)) : "memory")

#define MBARRIER_EXPECT_TX(mbar, bytes) \
    asm volatile("mbarrier.arrive.expect_tx.shared.b64 _, [%0], %1;" \
                 :: "r"(mbar), "r"((uint32_t)(bytes)) : "memory")

#define MBARRIER_WAIT_PARITY(mbar, parity) do { \
    uint32_t _mb = (mbar); \
    uint32_t _ph = (parity); \
    asm volatile( \
        "{\n\t" \
        ".reg .pred P1;\n\t" \
        "WAIT_LOOP_%=:\n\t" \
        "mbarrier.try_wait.parity.acquire.cta.shared::cta.b64 P1, [%0], %1, 0x989680;\n\t" \
        "@P1 bra.uni WAIT_DONE_%=;\n\t" \
        "bra.uni WAIT_LOOP_%=;\n\t" \
        "WAIT_DONE_%=:\n\t" \
        "}" \
        :: "r"(_mb), "r"(_ph) : "memory"); \
} while (0)

#define FENCE_PROXY_ASYNC() \
    asm volatile("fence.proxy.async.shared::cta;" ::: "memory")

// pack two fp32 -> f16x2 (e0 low, e1 high)
__device__ __forceinline__ uint32_t pack2h(float e0, float e1) {
    __half2 h = __floats2half2_rn(e0, e1);
    return *(uint32_t*)&h;
}

__device__ __forceinline__ void split2h(float e0, float e1,
                                        uint32_t& h, uint32_t& l) {
    h = pack2h(e0, e1);
    __half2 hh = *(__half2*)&h;
    l = pack2h(e0 - __low2float(hh), e1 - __high2float(hh));
}

__device__ __forceinline__ void split4h(float4 f, uint2& hi, uint2& lo) {
    split2h(f.x, f.y, hi.x, lo.x);
    split2h(f.z, f.w, hi.y, lo.y);
}

// Fast exp2 on the FMA pipe
__device__ __forceinline__ float exp2p(float y) {
    y = fmaxf(y, -126.0f);
    int n = __float2int_rd(y);
    float f = y - (float)n;
    float r = 1.8775767e-3f;
    r = fmaf(r, f, 8.9893397e-3f);
    r = fmaf(r, f, 5.5826318e-2f);
    r = fmaf(r, f, 2.4015361e-1f);
    r = fmaf(r, f, 6.9315308e-1f);
    r = fmaf(r, f, 1.0f);
    return r * __int_as_float((n + 127) << 23);
}

#define LOG2E 1.4426950408889634f

// ===========================================================================
// Split kernels: fp32 [nrows x 2048] -> tiled/swizzled fp16 (hi+lo or hi)
// ===========================================================================
__global__ __launch_bounds__(256) void split_tiled(
    const float* __restrict__ src, __half* __restrict__ hi,
    __half* __restrict__ lo, int nrows) {
    int idx = blockIdx.x * 256 + threadIdx.x;
    if (idx >= nrows * 256) return;
    int rg = idx >> 8;
    int g = idx & 255;
    int kc = g >> 3, c8 = g & 7;
    int panel = rg >> 7, r = rg & 127;

    const float4* s = (const float4*)(src + (size_t)rg * 2048 + kc * 64 + c8 * 8);
    float4 f0 = s[0], f1 = s[1];
    uint2 h0, l0, h1, l1;
    split4h(f0, h0, l0);
    split4h(f1, h1, l1);

    size_t off = (size_t)(panel * 32 + kc) * TB
               + (uint32_t)(r * 128 + ((c8 ^ (r & 7)) << 4));
    *(uint4*)((char*)hi + off) = make_uint4(h0.x, h0.y, h1.x, h1.y);
    *(uint4*)((char*)lo + off) = make_uint4(l0.x, l0.y, l1.x, l1.y);
}

__global__ __launch_bounds__(256) void split_tiled_h(
    const float* __restrict__ src, __half* __restrict__ hi, int nrows) {
    int idx = blockIdx.x * 256 + threadIdx.x;
    if (idx >= nrows * 256) return;
    int rg = idx >> 8;
    int g = idx & 255;
    int kc = g >> 3, c8 = g & 7;
    int panel = rg >> 7, r = rg & 127;

    const float4* s = (const float4*)(src + (size_t)rg * 2048 + kc * 64 + c8 * 8);
    float4 f0 = s[0], f1 = s[1];

    size_t off = (size_t)(panel * 32 + kc) * TB
               + (uint32_t)(r * 128 + ((c8 ^ (r & 7)) << 4));
    *(uint4*)((char*)hi + off) = make_uint4(pack2h(f0.x, f0.y), pack2h(f0.z, f0.w),
                                            pack2h(f1.x, f1.y), pack2h(f1.z, f1.w));
}

// ===========================================================================
// gemm6: C[M,Nn] = A @ W^T, fp16 2-MMA scheme (A = hi+lo, W = hi only).
// Tiled/swizzled inputs via cp.async.bulk, 3-stage mbarrier pipeline.
// CTA tile 128x128, BK=64, 256 threads, 8 warps (2m x 4n), warp tile 64x32.
// ===========================================================================
#define STB6   (3 * TB)            // bytes per stage (Ah, Al, Bh)
#define G6_MBAR (3 * STB6)
#define G6_SMEM (3 * STB6 + 32)    // 147456 + 32

__global__ __launch_bounds__(256) void gemm6(
    const __half* __restrict__ Ah, const __half* __restrict__ Al,
    const __half* __restrict__ Wh,
    float* __restrict__ C0, float* __restrict__ C1, float* __restrict__ C2,
    int Nn) {
    extern __shared__ char dsm[];
    const uint32_t sb = smem_u32(dsm);

    const int tid = threadIdx.x;
    const int warp = tid >> 5;
    const int lane = tid & 31;
    const int mbase = (warp >> 2) * 64;
    const int nbase = (warp & 3) * 32;

    const int z = blockIdx.z;
    float* C = (z == 0) ? C0 : (z == 1) ? C1 : C2;
    const char* pAh = (const char*)Ah;
    const char* pAl = (const char*)Al;
    const char* pBh = (const char*)(Wh + (size_t)z * D_SZ * D_SZ);

    float acc[4][4][4];
#pragma unroll
    for (int i = 0; i < 4; i++)
#pragma unroll
        for (int j = 0; j < 4; j++)
#pragma unroll
            for (int e = 0; e < 4; e++) acc[i][j][e] = 0.0f;

    const uint32_t mb0 = sb + G6_MBAR;

    if (tid == 0) {
        MBARRIER_INIT(mb0, 1);
        MBARRIER_INIT(mb0 + 8, 1);
        MBARRIER_INIT(mb0 + 16, 1);
    }
    __syncthreads();

    auto issue = [&](int st, int kc) {
        uint32_t s0 = sb + st * STB6;
        uint32_t mb = mb0 + st * 8;
        size_t offA = (size_t)(blockIdx.y * 32 + kc) * TB;
        size_t offB = (size_t)(blockIdx.x * 32 + kc) * TB;
        MBARRIER_EXPECT_TX(mb, 3 * TB);
        CP_BULK(s0,          pAh + offA, TB, mb);
        CP_BULK(s0 + TB,     pAl + offA, TB, mb);
        CP_BULK(s0 + 2 * TB, pBh + offB, TB, mb);
    };

    if (tid == 0) {
        issue(0, 0);
        issue(1, 1);
        issue(2, 2);
    }

    const int g = lane >> 3, lr = lane & 7;
    const uint32_t arow = (uint32_t)(mbase + lr + ((g & 1) << 3));
    const uint32_t brow = (uint32_t)(nbase + lr + ((g >> 1) << 3));
    const uint32_t aswz = arow & 7, bswz = brow & 7;

    for (int kc = 0; kc < 32; kc++) {
        const int st = kc % 3;
        MBARRIER_WAIT_PARITY(mb0 + st * 8, (kc / 3) & 1);

        const uint32_t uAh = sb + st * STB6;
        const uint32_t uAl = uAh + TB;
        const uint32_t uBh = uAh + 2 * TB;

#pragma unroll
        for (int s = 0; s < 4; s++) {
            uint32_t c8a = (uint32_t)(s * 2 + (g >> 1));
            uint32_t c8b = (uint32_t)(s * 2 + (g & 1));
            uint32_t aoff = arow * 128 + ((c8a ^ aswz) << 4);
            uint32_t boff = brow * 128 + ((c8b ^ bswz) << 4);

            uint32_t ah[4][4], al[4][4];
#pragma unroll
            for (int mi = 0; mi < 4; mi++) {
                ldsm_x4(ah[mi][0], ah[mi][1], ah[mi][2], ah[mi][3],
                        uAh + aoff + mi * 2048);
                ldsm_x4(al[mi][0], al[mi][1], al[mi][2], al[mi][3],
                        uAl + aoff + mi * 2048);
            }
            uint32_t bh[8];
            ldsm_x4(bh[0], bh[1], bh[2], bh[3], uBh + boff);
            ldsm_x4(bh[4], bh[5], bh[6], bh[7], uBh + boff + 2048);

#pragma unroll
            for (int mi = 0; mi < 4; mi++) {
#pragma unroll
                for (int ni = 0; ni < 4; ni++) {
                    mma_f16(acc[mi][ni], ah[mi], bh[ni * 2], bh[ni * 2 + 1]);
                    mma_f16(acc[mi][ni], al[mi], bh[ni * 2], bh[ni * 2 + 1]);
                }
            }
        }
        __syncthreads();
        if (kc + 3 < 32 && tid == 0) {
            FENCE_PROXY_ASYNC();
            issue(st, kc + 3);
        }
    }

    const int gid = lane >> 2, tig = lane & 3;
    const int rowA = blockIdx.y * 128 + mbase + gid;
    const int colA = blockIdx.x * 128 + nbase + tig * 2;
#pragma unroll
    for (int mi = 0; mi < 4; mi++) {
#pragma unroll
        for (int ni = 0; ni < 4; ni++) {
            float* c0 = C + (size_t)(rowA + mi * 16) * Nn + colA + ni * 8;
            float* c1 = C + (size_t)(rowA + mi * 16 + 8) * Nn + colA + ni * 8;
            c0[0] = acc[mi][ni][0];
            c0[1] = acc[mi][ni][1];
            c1[0] = acc[mi][ni][2];
            c1[1] = acc[mi][ni][3];
        }
    }
}

// ---------------------------------------------------------------------------
// RoPE (in-place on g_q, g_k)
// ---------------------------------------------------------------------------
__global__ __launch_bounds__(256) void rope_kernel(float* __restrict__ q,
                                                   float* __restrict__ k) {
    int idx = blockIdx.x * blockDim.x + threadIdx.x;
    const int total = M_SZ * H_SZ * (HD_SZ / 2);
    if (idx >= total) return;

    int i = idx & 63;
    int h = (idx >> 6) & 15;
    int m = idx >> 10;
    int pos = m & (N_SZ - 1);

    float inv_freq = powf(10000.0f, -(float)i * (1.0f / 64.0f));
    float f = (float)pos * inv_freq;
    float s, c;
    sincosf(f, &s, &c);

    size_t base = (size_t)m * D_SZ + h * HD_SZ;
    float q1 = q[base + i], q2 = q[base + 64 + i];
    q[base + i]      = q1 * c - q2 * s;
    q[base + 64 + i] = q2 * c + q1 * s;

    float k1 = k[base + i], k2 = k[base + 64 + i];
    k[base + i]      = k1 * c - k2 * s;
    k[base + 64 + i] = k2 * c + k1 * s;
}

// ===========================================================================
// HMMA flash attention, fp16 2-MMA: Q = hi+lo, K = hi, V = hi, P = hi+lo.
// fp32 q/k/v in, TILED fp16 hi/lo O out.
// ===========================================================================
#define SROW   136
#define SROWB  272
#define AMAT   (128 * SROW)
#define ATT_SMEM (4 * AMAT * 2)    // 139264

__global__ __launch_bounds__(256) void attn_hmma(
    const float* __restrict__ q, const float* __restrict__ k,
    const float* __restrict__ v,
    __half* __restrict__ oh, __half* __restrict__ ol) {
    extern __shared__ uint16_t sm[];
    uint16_t* Qh = sm;
    uint16_t* Ql = sm + AMAT;
    uint16_t* Kh = sm + 2 * AMAT;
    uint16_t* Vh = sm + 3 * AMAT;
    const uint32_t uQh = smem_u32(Qh), uQl = smem_u32(Ql);
    const uint32_t uKh = smem_u32(Kh), uVh = smem_u32(Vh);

    const int bh = blockIdx.y;
    const int b = bh >> 4, h = bh & 15;
    const int q0 = blockIdx.x * 128;
    const int tid = threadIdx.x;
    const int warp = tid >> 5, lane = tid & 31;
    const int g8 = lane >> 3, lr = lane & 7;
    const int g4 = lane >> 2, t4 = lane & 3;

    const float scale = 0.08838834764831845f;

    const float* qb = q + (size_t)(b * N_SZ + q0) * D_SZ + h * HD_SZ;
#pragma unroll
    for (int it = 0; it < 16; it++) {
        int e = tid + it * 256;
        int r = e >> 5, c4 = e & 31;
        float4 f = *(const float4*)(qb + (size_t)r * D_SZ + c4 * 4);
        f.x *= scale; f.y *= scale; f.z *= scale; f.w *= scale;
        uint2 hi, lo;
        split4h(f, hi, lo);
        *(uint2*)((char*)Qh + r * SROWB + c4 * 8) = hi;
        *(uint2*)((char*)Ql + r * SROWB + c4 * 8) = lo;
    }

    float accO[16][4];
#pragma unroll
    for (int nd = 0; nd < 16; nd++)
#pragma unroll
        for (int e = 0; e < 4; e++) accO[nd][e] = 0.0f;
    float m0 = -1e30f, m1 = -1e30f, l0 = 0.0f, l1 = 0.0f;

    for (int kt = 0; kt < N_SZ / 128; kt++) {
        __syncthreads();
        const float* kb = k + (size_t)(b * N_SZ + kt * 128) * D_SZ + h * HD_SZ;
        const float* vb = v + (size_t)(b * N_SZ + kt * 128) * D_SZ + h * HD_SZ;
#pragma unroll
        for (int it = 0; it < 16; it++) {
            int e = tid + it * 256;
            int r = e >> 5, c4 = e & 31;
            float4 fk = *(const float4*)(kb + (size_t)r * D_SZ + c4 * 4);
            *(uint2*)((char*)Kh + r * SROWB + c4 * 8) =
                make_uint2(pack2h(fk.x, fk.y), pack2h(fk.z, fk.w));
            float4 fv = *(const float4*)(vb + (size_t)r * D_SZ + c4 * 4);
            *(uint2*)((char*)Vh + r * SROWB + c4 * 8) =
                make_uint2(pack2h(fv.x, fv.y), pack2h(fv.z, fv.w));
        }
        __syncthreads();

        float acc[16][4];
#pragma unroll
        for (int nt = 0; nt < 16; nt++)
#pragma unroll
            for (int e = 0; e < 4; e++) acc[nt][e] = 0.0f;

        {
            const uint32_t arow = (uint32_t)(warp * 16 + lr + ((g8 & 1) << 3));
            const uint32_t brow_g = (uint32_t)(lr + ((g8 >> 1) << 3));
#pragma unroll
            for (int ks = 0; ks < 8; ks++) {
                uint32_t acol = (uint32_t)(ks * 32 + ((g8 >> 1) << 4));
                uint32_t qhh[4], qll[4];
                ldsm_x4(qhh[0], qhh[1], qhh[2], qhh[3], uQh + arow * SROWB + acol);
                ldsm_x4(qll[0], qll[1], qll[2], qll[3], uQl + arow * SROWB + acol);
                uint32_t bcol = (uint32_t)(ks * 32 + ((g8 & 1) << 4));
#pragma unroll
                for (int np = 0; np < 8; np++) {
                    uint32_t boff = (np * 16 + brow_g) * SROWB + bcol;
                    uint32_t kh[4];
                    ldsm_x4(kh[0], kh[1], kh[2], kh[3], uKh + boff);
                    mma_f16(acc[2 * np],     qhh, kh[0], kh[1]);
                    mma_f16(acc[2 * np + 1], qhh, kh[2], kh[3]);
                    mma_f16(acc[2 * np],     qll, kh[0], kh[1]);
                    mma_f16(acc[2 * np + 1], qll, kh[2], kh[3]);
                }
            }
        }

        float mx0 = -1e30f, mx1 = -1e30f;
#pragma unroll
        for (int nt = 0; nt < 16; nt++) {
            mx0 = fmaxf(mx0, fmaxf(acc[nt][0], acc[nt][1]));
            mx1 = fmaxf(mx1, fmaxf(acc[nt][2], acc[nt][3]));
        }
        mx0 = fmaxf(mx0, __shfl_xor_sync(0xFFFFFFFFu, mx0, 1));
        mx0 = fmaxf(mx0, __shfl_xor_sync(0xFFFFFFFFu, mx0, 2));
        mx1 = fmaxf(mx1, __shfl_xor_sync(0xFFFFFFFFu, mx1, 1));
        mx1 = fmaxf(mx1, __shfl_xor_sync(0xFFFFFFFFu, mx1, 2));
        float mn0 = fmaxf(m0, mx0), mn1 = fmaxf(m1, mx1);
        float corr0 = exp2p((m0 - mn0) * LOG2E);
        float corr1 = exp2p((m1 - mn1) * LOG2E);
        m0 = mn0; m1 = mn1;

        float sum0 = 0.0f, sum1 = 0.0f;
#pragma unroll
        for (int nt = 0; nt < 16; nt++) {
            acc[nt][0] = exp2p((acc[nt][0] - mn0) * LOG2E);
            acc[nt][1] = exp2p((acc[nt][1] - mn0) * LOG2E);
            acc[nt][2] = exp2p((acc[nt][2] - mn1) * LOG2E);
            acc[nt][3] = exp2p((acc[nt][3] - mn1) * LOG2E);
            sum0 += acc[nt][0] + acc[nt][1];
            sum1 += acc[nt][2] + acc[nt][3];
        }
        sum0 += __shfl_xor_sync(0xFFFFFFFFu, sum0, 1);
        sum0 += __shfl_xor_sync(0xFFFFFFFFu, sum0, 2);
        sum1 += __shfl_xor_sync(0xFFFFFFFFu, sum1, 1);
        sum1 += __shfl_xor_sync(0xFFFFFFFFu, sum1, 2);
        l0 = l0 * corr0 + sum0;
        l1 = l1 * corr1 + sum1;

#pragma unroll
        for (int nd = 0; nd < 16; nd++) {
            accO[nd][0] *= corr0; accO[nd][1] *= corr0;
            accO[nd][2] *= corr1; accO[nd][3] *= corr1;
        }

        const uint32_t vrow_g = (uint32_t)(lr + ((g8 & 1) << 3));
        const uint32_t vcol_g = (uint32_t)((g8 >> 1) << 4);
#pragma unroll
        for (int kk = 0; kk < 8; kk++) {
            uint32_t pah[4], pal[4];
            {
                int n0 = 2 * kk, n1 = 2 * kk + 1;
                split2h(acc[n0][0], acc[n0][1], pah[0], pal[0]);
                split2h(acc[n0][2], acc[n0][3], pah[1], pal[1]);
                split2h(acc[n1][0], acc[n1][1], pah[2], pal[2]);
                split2h(acc[n1][2], acc[n1][3], pah[3], pal[3]);
            }
            uint32_t vbase_row = (uint32_t)(kk * 16) + vrow_g;
#pragma unroll
            for (int half = 0; half < 2; half++) {
                uint32_t vh[4][4];
#pragma unroll
                for (int j = 0; j < 4; j++) {
                    uint32_t ndp = half * 4 + j;
                    uint32_t voff = vbase_row * SROWB + ndp * 32 + vcol_g;
                    ldsm_x4_t(vh[j][0], vh[j][1], vh[j][2], vh[j][3], uVh + voff);
                }
#pragma unroll
                for (int j = 0; j < 4; j++) {
                    int nda = (half * 4 + j) * 2, ndb = nda + 1;
                    mma_f16(accO[nda], pah, vh[j][0], vh[j][1]);
                    mma_f16(accO[ndb], pah, vh[j][2], vh[j][3]);
                    mma_f16(accO[nda], pal, vh[j][0], vh[j][1]);
                    mma_f16(accO[ndb], pal, vh[j][2], vh[j][3]);
                }
            }
        }
    }

    // ---- Epilogue: normalize, split fp16, write TILED hi/lo layout ----
    float inv0 = 1.0f / l0, inv1 = 1.0f / l1;
    const int mrow0 = b * N_SZ + q0 + warp * 16 + g4;   // row1 = +8
    const int panel = mrow0 >> 7;
    const int r0 = mrow0 & 127;
    const uint32_t rsw = (uint32_t)(r0 & 7);
#pragma unroll
    for (int nd = 0; nd < 16; nd++) {
        int kchunk = h * 2 + (nd >> 3);
        uint32_t c8 = (uint32_t)(nd & 7);
        size_t blk = (size_t)(panel * 32 + kchunk) * TB;
        uint32_t in0 = (uint32_t)(r0 * 128) + ((c8 ^ rsw) << 4) + t4 * 4;
        uint32_t hw, lw;
        split2h(accO[nd][0] * inv0, accO[nd][1] * inv0, hw, lw);
        *(uint32_t*)((char*)oh + blk + in0) = hw;
        *(uint32_t*)((char*)ol + blk + in0) = lw;
        split2h(accO[nd][2] * inv1, accO[nd][3] * inv1, hw, lw);
        *(uint32_t*)((char*)oh + blk + in0 + 1024) = hw;
        *(uint32_t*)((char*)ol + blk + in0 + 1024) = lw;
    }
}

// ---------------------------------------------------------------------------
// Launch
// ---------------------------------------------------------------------------
extern "C" void kernel_launch(void* const* d_in, const int* in_sizes, int n_in,
                              void* d_out, int out_size) {
    const float* x  = (const float*)d_in[0];
    const float* Wq = (const float*)d_in[1];
    const float* Wk = (const float*)d_in[2];
    const float* Wv = (const float*)d_in[3];
    const float* Wo = (const float*)d_in[4];
    float* out = (float*)d_out;

    float *q_ptr, *k_ptr, *v_ptr;
    __half *xh, *xl, *wh, *oh, *ol;
    cudaGetSymbolAddress((void**)&q_ptr, g_q);
    cudaGetSymbolAddress((void**)&k_ptr, g_k);
    cudaGetSymbolAddress((void**)&v_ptr, g_v);
    cudaGetSymbolAddress((void**)&xh, g_xh);
    cudaGetSymbolAddress((void**)&xl, g_xl);
    cudaGetSymbolAddress((void**)&wh, g_wh);
    cudaGetSymbolAddress((void**)&oh, g_oh);
    cudaGetSymbolAddress((void**)&ol, g_ol);

    cudaFuncSetAttribute(gemm6, cudaFuncAttributeMaxDynamicSharedMemorySize,
                         G6_SMEM);
    cudaFuncSetAttribute(attn_hmma, cudaFuncAttributeMaxDynamicSharedMemorySize,
                         ATT_SMEM);

    const size_t woff = (size_t)D_SZ * D_SZ;

    // Pre-split + tile operands (weights: hi only)
    split_tiled<<<M_SZ, 256>>>(x, xh, xl, M_SZ);
    split_tiled_h<<<D_SZ, 256>>>(Wq, wh, D_SZ);
    split_tiled_h<<<D_SZ, 256>>>(Wk, wh + woff, D_SZ);
    split_tiled_h<<<D_SZ, 256>>>(Wv, wh + 2 * woff, D_SZ);
    split_tiled_h<<<D_SZ, 256>>>(Wo, wh + 3 * woff, D_SZ);

    // Fused Q/K/V projection
    dim3 gq(D_SZ / 128, M_SZ / 128, 3);    // (16, 32, 3)
    gemm6<<<gq, 256, G6_SMEM>>>(xh, xl, wh, q_ptr, k_ptr, v_ptr, D_SZ);

    int rope_total = M_SZ * H_SZ * (HD_SZ / 2);
    rope_kernel<<<(rope_total + 255) / 256, 256>>>(q_ptr, k_ptr);

    dim3 ga(N_SZ / 128, B_SZ * H_SZ);      // (16, 32)
    attn_hmma<<<ga, 256, ATT_SMEM>>>(q_ptr, k_ptr, v_ptr, oh, ol);

    // O projection
    dim3 go(D_SZ / 128, M_SZ / 128, 1);
    gemm6<<<go, 256, G6_SMEM>>>(oh, ol, wh + 3 * woff, out, out, out, D_SZ);
}

// round 11
// speedup vs baseline: 6.5292x; 1.2096x over previous
#include <cuda_runtime.h>
#include <cuda_fp16.h>
#include <cstdint>

#define B_SZ 2
#define N_SZ 2048
#define D_SZ 2048
#define H_SZ 16
#define HD_SZ 128
#define M_SZ (B_SZ * N_SZ)   // 4096

// Tiled operand layout: 16KB blocks [128 rows x 64 cols f16], row stride
// 128 B, 16B-group swizzle c8 ^= (r & 7). Block id = panel*32 + kchunk.
#define TB 16384

// Scratch (static device arrays; no allocation allowed)
__device__ float g_q[M_SZ * D_SZ];
__device__ float g_k[M_SZ * D_SZ];
__device__ float g_v[M_SZ * D_SZ];
__device__ __align__(128) __half g_xh[M_SZ * D_SZ];
__device__ __align__(128) __half g_xl[M_SZ * D_SZ];
__device__ __align__(128) __half g_wh[4 * D_SZ * D_SZ];
__device__ __align__(128) __half g_oh[M_SZ * D_SZ];
__device__ __align__(128) __half g_ol[M_SZ * D_SZ];
__device__ __align__(128) __half g_qh[M_SZ * D_SZ];
__device__ __align__(128) __half g_ql[M_SZ * D_SZ];
__device__ __align__(128) __half g_kh[M_SZ * D_SZ];
__device__ __align__(128) __half g_vh[M_SZ * D_SZ];

// ===========================================================================
// PTX helpers (sm_80/sm_90 base-arch: legal at compute_103)
// ===========================================================================
__device__ __forceinline__ uint32_t smem_u32(const void* p) {
    uint32_t a;
    asm("{ .reg .u64 t; cvta.to.shared.u64 t, %1; cvt.u32.u64 %0, t; }"
        : "=r"(a) : "l"(p));
    return a;
}

__device__ __forceinline__ void ldsm_x4(uint32_t& r0, uint32_t& r1,
                                        uint32_t& r2, uint32_t& r3,
                                        uint32_t addr) {
    asm volatile("ldmatrix.sync.aligned.m8n8.x4.shared.b16 {%0,%1,%2,%3}, [%4];"
                 : "=r"(r0), "=r"(r1), "=r"(r2), "=r"(r3) : "r"(addr));
}

__device__ __forceinline__ void ldsm_x4_t(uint32_t& r0, uint32_t& r1,
                                          uint32_t& r2, uint32_t& r3,
                                          uint32_t addr) {
    asm volatile("ldmatrix.sync.aligned.m8n8.x4.trans.shared.b16 {%0,%1,%2,%3}, [%4];"
                 : "=r"(r0), "=r"(r1), "=r"(r2), "=r"(r3) : "r"(addr));
}

__device__ __forceinline__ void mma_f16(float* d, const uint32_t* a,
                                        uint32_t b0, uint32_t b1) {
    asm volatile(
        "mma.sync.aligned.m16n8k16.row.col.f32.f16.f16.f32 "
        "{%0,%1,%2,%3}, {%4,%5,%6,%7}, {%8,%9}, {%0,%1,%2,%3};"
        : "+f"(d[0]), "+f"(d[1]), "+f"(d[2]), "+f"(d[3])
        : "r"(a[0]), "r"(a[1]), "r"(a[2]), "r"(a[3]), "r"(b0), "r"(b1));
}

// Non-tensor bulk TMA: contiguous global -> contiguous shared
#define CP_BULK(saddr, gptr, bytes, mbar) \
    asm volatile( \
        "cp.async.bulk.shared::cta.global.mbarrier::complete_tx::bytes " \
        "[%0], [%1], %2, [%3];" \
        :: "r"(saddr), "l"(gptr), "r"(bytes), "r"(mbar) : "memory")

#define MBARRIER_INIT(mbar, count) \
    asm volatile("mbarrier.init.shared.b64 [%0], %1;" \
                 :: "r"(mbar), "r"((uint32_t)(count)) : "memory")

#define MBARRIER_EXPECT_TX(mbar, bytes) \
    asm volatile("mbarrier.arrive.expect_tx.shared.b64 _, [%0], %1;" \
                 :: "r"(mbar), "r"((uint32_t)(bytes)) : "memory")

#define MBARRIER_WAIT_PARITY(mbar, parity) do { \
    uint32_t _mb = (mbar); \
    uint32_t _ph = (parity); \
    asm volatile( \
        "{\n\t" \
        ".reg .pred P1;\n\t" \
        "WAIT_LOOP_%=:\n\t" \
        "mbarrier.try_wait.parity.acquire.cta.shared::cta.b64 P1, [%0], %1, 0x989680;\n\t" \
        "@P1 bra.uni WAIT_DONE_%=;\n\t" \
        "bra.uni WAIT_LOOP_%=;\n\t" \
        "WAIT_DONE_%=:\n\t" \
        "}" \
        :: "r"(_mb), "r"(_ph) : "memory"); \
} while (0)

#define FENCE_PROXY_ASYNC() \
    asm volatile("fence.proxy.async.shared::cta;" ::: "memory")

// pack two fp32 -> f16x2 (e0 low, e1 high)
__device__ __forceinline__ uint32_t pack2h(float e0, float e1) {
    __half2 h = __floats2half2_rn(e0, e1);
    return *(uint32_t*)&h;
}

__device__ __forceinline__ void split2h(float e0, float e1,
                                        uint32_t& h, uint32_t& l) {
    h = pack2h(e0, e1);
    __half2 hh = *(__half2*)&h;
    l = pack2h(e0 - __low2float(hh), e1 - __high2float(hh));
}

__device__ __forceinline__ void split4h(float4 f, uint2& hi, uint2& lo) {
    split2h(f.x, f.y, hi.x, lo.x);
    split2h(f.z, f.w, hi.y, lo.y);
}

// Fast exp2 on the FMA pipe
__device__ __forceinline__ float exp2p(float y) {
    y = fmaxf(y, -126.0f);
    int n = __float2int_rd(y);
    float f = y - (float)n;
    float r = 1.8775767e-3f;
    r = fmaf(r, f, 8.9893397e-3f);
    r = fmaf(r, f, 5.5826318e-2f);
    r = fmaf(r, f, 2.4015361e-1f);
    r = fmaf(r, f, 6.9315308e-1f);
    r = fmaf(r, f, 1.0f);
    return r * __int_as_float((n + 127) << 23);
}

#define LOG2E 1.4426950408889634f

// ===========================================================================
// Split kernels: fp32 [nrows x 2048] -> tiled/swizzled fp16 (hi+lo or hi)
// ===========================================================================
__global__ __launch_bounds__(256) void split_tiled(
    const float* __restrict__ src, __half* __restrict__ hi,
    __half* __restrict__ lo, int nrows) {
    int idx = blockIdx.x * 256 + threadIdx.x;
    if (idx >= nrows * 256) return;
    int rg = idx >> 8;
    int g = idx & 255;
    int kc = g >> 3, c8 = g & 7;
    int panel = rg >> 7, r = rg & 127;

    const float4* s = (const float4*)(src + (size_t)rg * 2048 + kc * 64 + c8 * 8);
    float4 f0 = s[0], f1 = s[1];
    uint2 h0, l0, h1, l1;
    split4h(f0, h0, l0);
    split4h(f1, h1, l1);

    size_t off = (size_t)(panel * 32 + kc) * TB
               + (uint32_t)(r * 128 + ((c8 ^ (r & 7)) << 4));
    *(uint4*)((char*)hi + off) = make_uint4(h0.x, h0.y, h1.x, h1.y);
    *(uint4*)((char*)lo + off) = make_uint4(l0.x, l0.y, l1.x, l1.y);
}

__global__ __launch_bounds__(256) void split_tiled_h(
    const float* __restrict__ src, __half* __restrict__ hi, int nrows) {
    int idx = blockIdx.x * 256 + threadIdx.x;
    if (idx >= nrows * 256) return;
    int rg = idx >> 8;
    int g = idx & 255;
    int kc = g >> 3, c8 = g & 7;
    int panel = rg >> 7, r = rg & 127;

    const float4* s = (const float4*)(src + (size_t)rg * 2048 + kc * 64 + c8 * 8);
    float4 f0 = s[0], f1 = s[1];

    size_t off = (size_t)(panel * 32 + kc) * TB
               + (uint32_t)(r * 128 + ((c8 ^ (r & 7)) << 4));
    *(uint4*)((char*)hi + off) = make_uint4(pack2h(f0.x, f0.y), pack2h(f0.z, f0.w),
                                            pack2h(f1.x, f1.y), pack2h(f1.z, f1.w));
}

// ===========================================================================
// rope_convert: read fp32 q/k/v, apply RoPE to q/k (+1/sqrt(d) scale on q),
// write tiled/swizzled fp16: Q hi+lo, K hi, V hi.
// Thread = (row, head, 8-col group in first half); partner cols at +64.
// ===========================================================================
__global__ __launch_bounds__(256) void rope_convert(
    const float* __restrict__ q, const float* __restrict__ k,
    const float* __restrict__ v,
    __half* __restrict__ qh, __half* __restrict__ ql,
    __half* __restrict__ kh, __half* __restrict__ vh) {
    int idx = blockIdx.x * 256 + threadIdx.x;     // M*16*8 = 524288
    int rg = idx >> 7;
    int rem = idx & 127;
    int h = rem >> 3, c8 = rem & 7;
    int pos = rg & (N_SZ - 1);
    int panel = rg >> 7, r = rg & 127;
    const float sc = 0.08838834764831845f;

    float cc[8], ss[8];
#pragma unroll
    for (int e = 0; e < 8; e++) {
        int i = c8 * 8 + e;
        float inv_freq = powf(10000.0f, -(float)i * (1.0f / 64.0f));
        sincosf((float)pos * inv_freq, &ss[e], &cc[e]);
    }

    size_t base = (size_t)rg * D_SZ + h * HD_SZ + c8 * 8;
    float q1[8], q2[8], k1[8], k2[8], v1[8], v2[8];
    *(float4*)&q1[0] = *(const float4*)(q + base);
    *(float4*)&q1[4] = *(const float4*)(q + base + 4);
    *(float4*)&q2[0] = *(const float4*)(q + base + 64);
    *(float4*)&q2[4] = *(const float4*)(q + base + 68);
    *(float4*)&k1[0] = *(const float4*)(k + base);
    *(float4*)&k1[4] = *(const float4*)(k + base + 4);
    *(float4*)&k2[0] = *(const float4*)(k + base + 64);
    *(float4*)&k2[4] = *(const float4*)(k + base + 68);
    *(float4*)&v1[0] = *(const float4*)(v + base);
    *(float4*)&v1[4] = *(const float4*)(v + base + 4);
    *(float4*)&v2[0] = *(const float4*)(v + base + 64);
    *(float4*)&v2[4] = *(const float4*)(v + base + 68);

    float qo1[8], qo2[8], ko1[8], ko2[8];
#pragma unroll
    for (int e = 0; e < 8; e++) {
        qo1[e] = (q1[e] * cc[e] - q2[e] * ss[e]) * sc;
        qo2[e] = (q2[e] * cc[e] + q1[e] * ss[e]) * sc;
        ko1[e] = k1[e] * cc[e] - k2[e] * ss[e];
        ko2[e] = k2[e] * cc[e] + k1[e] * ss[e];
    }

    uint32_t inoff = (uint32_t)(r * 128 + ((c8 ^ (r & 7)) << 4));
    size_t b0 = (size_t)(panel * 32 + 2 * h) * TB + inoff;
    size_t b1 = b0 + TB;

    uint32_t hw0, lw0, hw1, lw1, hw2, lw2, hw3, lw3;
    split2h(qo1[0], qo1[1], hw0, lw0);
    split2h(qo1[2], qo1[3], hw1, lw1);
    split2h(qo1[4], qo1[5], hw2, lw2);
    split2h(qo1[6], qo1[7], hw3, lw3);
    *(uint4*)((char*)qh + b0) = make_uint4(hw0, hw1, hw2, hw3);
    *(uint4*)((char*)ql + b0) = make_uint4(lw0, lw1, lw2, lw3);
    split2h(qo2[0], qo2[1], hw0, lw0);
    split2h(qo2[2], qo2[3], hw1, lw1);
    split2h(qo2[4], qo2[5], hw2, lw2);
    split2h(qo2[6], qo2[7], hw3, lw3);
    *(uint4*)((char*)qh + b1) = make_uint4(hw0, hw1, hw2, hw3);
    *(uint4*)((char*)ql + b1) = make_uint4(lw0, lw1, lw2, lw3);

    *(uint4*)((char*)kh + b0) = make_uint4(pack2h(ko1[0], ko1[1]), pack2h(ko1[2], ko1[3]),
                                           pack2h(ko1[4], ko1[5]), pack2h(ko1[6], ko1[7]));
    *(uint4*)((char*)kh + b1) = make_uint4(pack2h(ko2[0], ko2[1]), pack2h(ko2[2], ko2[3]),
                                           pack2h(ko2[4], ko2[5]), pack2h(ko2[6], ko2[7]));
    *(uint4*)((char*)vh + b0) = make_uint4(pack2h(v1[0], v1[1]), pack2h(v1[2], v1[3]),
                                           pack2h(v1[4], v1[5]), pack2h(v1[6], v1[7]));
    *(uint4*)((char*)vh + b1) = make_uint4(pack2h(v2[0], v2[1]), pack2h(v2[2], v2[3]),
                                           pack2h(v2[4], v2[5]), pack2h(v2[6], v2[7]));
}

// ===========================================================================
// gemm7: C[M,Nn] = A @ W^T, fp16 2-MMA (A = hi+lo, W = hi). cp.async.bulk,
// 2-stage (96KB smem) -> 2 CTAs/SM. CTA tile 128x128, BK=64, 256 threads.
// ===========================================================================
#define STB7   (3 * TB)            // bytes per stage (Ah, Al, Bh)
#define G7_MBAR (2 * STB7)
#define G7_SMEM (2 * STB7 + 32)    // 98336

__global__ __launch_bounds__(256, 2) void gemm7(
    const __half* __restrict__ Ah, const __half* __restrict__ Al,
    const __half* __restrict__ Wh,
    float* __restrict__ C0, float* __restrict__ C1, float* __restrict__ C2,
    int Nn) {
    extern __shared__ char dsm[];
    const uint32_t sb = smem_u32(dsm);

    const int tid = threadIdx.x;
    const int warp = tid >> 5;
    const int lane = tid & 31;
    const int mbase = (warp >> 2) * 64;
    const int nbase = (warp & 3) * 32;

    const int z = blockIdx.z;
    float* C = (z == 0) ? C0 : (z == 1) ? C1 : C2;
    const char* pAh = (const char*)Ah;
    const char* pAl = (const char*)Al;
    const char* pBh = (const char*)(Wh + (size_t)z * D_SZ * D_SZ);

    float acc[4][4][4];
#pragma unroll
    for (int i = 0; i < 4; i++)
#pragma unroll
        for (int j = 0; j < 4; j++)
#pragma unroll
            for (int e = 0; e < 4; e++) acc[i][j][e] = 0.0f;

    const uint32_t mb0 = sb + G7_MBAR;

    if (tid == 0) {
        MBARRIER_INIT(mb0, 1);
        MBARRIER_INIT(mb0 + 8, 1);
    }
    __syncthreads();

    auto issue = [&](int st, int kc) {
        uint32_t s0 = sb + st * STB7;
        uint32_t mb = mb0 + st * 8;
        size_t offA = (size_t)(blockIdx.y * 32 + kc) * TB;
        size_t offB = (size_t)(blockIdx.x * 32 + kc) * TB;
        MBARRIER_EXPECT_TX(mb, 3 * TB);
        CP_BULK(s0,          pAh + offA, TB, mb);
        CP_BULK(s0 + TB,     pAl + offA, TB, mb);
        CP_BULK(s0 + 2 * TB, pBh + offB, TB, mb);
    };

    if (tid == 0) {
        issue(0, 0);
        issue(1, 1);
    }

    const int g = lane >> 3, lr = lane & 7;
    const uint32_t arow = (uint32_t)(mbase + lr + ((g & 1) << 3));
    const uint32_t brow = (uint32_t)(nbase + lr + ((g >> 1) << 3));
    const uint32_t aswz = arow & 7, bswz = brow & 7;

    for (int kc = 0; kc < 32; kc++) {
        const int st = kc & 1;
        MBARRIER_WAIT_PARITY(mb0 + st * 8, (kc >> 1) & 1);

        const uint32_t uAh = sb + st * STB7;
        const uint32_t uAl = uAh + TB;
        const uint32_t uBh = uAh + 2 * TB;

#pragma unroll
        for (int s = 0; s < 4; s++) {
            uint32_t c8a = (uint32_t)(s * 2 + (g >> 1));
            uint32_t c8b = (uint32_t)(s * 2 + (g & 1));
            uint32_t aoff = arow * 128 + ((c8a ^ aswz) << 4);
            uint32_t boff = brow * 128 + ((c8b ^ bswz) << 4);

            uint32_t ah[4][4], al[4][4];
#pragma unroll
            for (int mi = 0; mi < 4; mi++) {
                ldsm_x4(ah[mi][0], ah[mi][1], ah[mi][2], ah[mi][3],
                        uAh + aoff + mi * 2048);
                ldsm_x4(al[mi][0], al[mi][1], al[mi][2], al[mi][3],
                        uAl + aoff + mi * 2048);
            }
            uint32_t bh[8];
            ldsm_x4(bh[0], bh[1], bh[2], bh[3], uBh + boff);
            ldsm_x4(bh[4], bh[5], bh[6], bh[7], uBh + boff + 2048);

#pragma unroll
            for (int mi = 0; mi < 4; mi++) {
#pragma unroll
                for (int ni = 0; ni < 4; ni++) {
                    mma_f16(acc[mi][ni], ah[mi], bh[ni * 2], bh[ni * 2 + 1]);
                    mma_f16(acc[mi][ni], al[mi], bh[ni * 2], bh[ni * 2 + 1]);
                }
            }
        }
        __syncthreads();
        if (kc + 2 < 32 && tid == 0) {
            FENCE_PROXY_ASYNC();
            issue(st, kc + 2);
        }
    }

    const int gid = lane >> 2, tig = lane & 3;
    const int rowA = blockIdx.y * 128 + mbase + gid;
    const int colA = blockIdx.x * 128 + nbase + tig * 2;
#pragma unroll
    for (int mi = 0; mi < 4; mi++) {
#pragma unroll
        for (int ni = 0; ni < 4; ni++) {
            float* c0 = C + (size_t)(rowA + mi * 16) * Nn + colA + ni * 8;
            float* c1 = C + (size_t)(rowA + mi * 16 + 8) * Nn + colA + ni * 8;
            c0[0] = acc[mi][ni][0];
            c0[1] = acc[mi][ni][1];
            c1[0] = acc[mi][ni][2];
            c1[1] = acc[mi][ni][3];
        }
    }
}

// ===========================================================================
// attn2: flash attention on pre-converted tiled fp16 operands.
// Q(hi+lo) loaded once; K/V(hi) double-buffered via cp.async.bulk.
// SMEM: Qh 32K | Ql 32K | stage0 {K 32K, V 32K} | stage1 {K 32K, V 32K}.
// ===========================================================================
#define ATT2_SMEM (12 * TB + 64)   // 196672

__global__ __launch_bounds__(256, 1) void attn2(
    const __half* __restrict__ qh, const __half* __restrict__ ql,
    const __half* __restrict__ kh, const __half* __restrict__ vh,
    __half* __restrict__ oh, __half* __restrict__ ol) {
    extern __shared__ char smc[];
    const uint32_t sb = smem_u32(smc);
    const uint32_t uQh = sb, uQl = sb + 2 * TB;
    const uint32_t mbQ = sb + 12 * TB;        // +0: Q, +8: st0, +16: st1

    const int bh = blockIdx.y;
    const int b = bh >> 4, h = bh & 15;
    const int qt = blockIdx.x;
    const int tid = threadIdx.x;
    const int warp = tid >> 5, lane = tid & 31;
    const int g8 = lane >> 3, lr = lane & 7;
    const int g4 = lane >> 2, t4 = lane & 3;

    if (tid == 0) {
        MBARRIER_INIT(mbQ, 1);
        MBARRIER_INIT(mbQ + 8, 1);
        MBARRIER_INIT(mbQ + 16, 1);
    }
    __syncthreads();

    auto issueKV = [&](int st, int kt) {
        uint32_t s0 = sb + 4 * TB + st * (4 * TB);
        uint32_t mb = mbQ + 8 + st * 8;
        size_t off = (size_t)((b * 16 + kt) * 32 + 2 * h) * TB;
        MBARRIER_EXPECT_TX(mb, 4 * TB);
        CP_BULK(s0,          (const char*)kh + off, 2 * TB, mb);
        CP_BULK(s0 + 2 * TB, (const char*)vh + off, 2 * TB, mb);
    };

    if (tid == 0) {
        size_t qoff = (size_t)((b * 16 + qt) * 32 + 2 * h) * TB;
        MBARRIER_EXPECT_TX(mbQ, 4 * TB);
        CP_BULK(uQh, (const char*)qh + qoff, 2 * TB, mbQ);
        CP_BULK(uQl, (const char*)ql + qoff, 2 * TB, mbQ);
        issueKV(0, 0);
        issueKV(1, 1);
    }

    float accO[16][4];
#pragma unroll
    for (int nd = 0; nd < 16; nd++)
#pragma unroll
        for (int e = 0; e < 4; e++) accO[nd][e] = 0.0f;
    float m0 = -1e30f, m1 = -1e30f, l0 = 0.0f, l1 = 0.0f;

    const uint32_t arow = (uint32_t)(warp * 16 + lr + ((g8 & 1) << 3));
    const uint32_t ulr = (uint32_t)lr;    // swizzle sel for all our rows

    MBARRIER_WAIT_PARITY(mbQ, 0);

    for (int kt = 0; kt < 16; kt++) {
        const int st = kt & 1;
        MBARRIER_WAIT_PARITY(mbQ + 8 + st * 8, (kt >> 1) & 1);
        const uint32_t uK = sb + 4 * TB + st * (4 * TB);
        const uint32_t uV = uK + 2 * TB;

        // ---- S = Q K^T ----
        float acc[16][4];
#pragma unroll
        for (int nt = 0; nt < 16; nt++)
#pragma unroll
            for (int e = 0; e < 4; e++) acc[nt][e] = 0.0f;

#pragma unroll
        for (int blk = 0; blk < 2; blk++) {
            const uint32_t uQhb = uQh + blk * TB;
            const uint32_t uQlb = uQl + blk * TB;
            const uint32_t uKb = uK + blk * TB;
#pragma unroll
            for (int s = 0; s < 4; s++) {
                uint32_t c8a = (uint32_t)(s * 2 + (g8 >> 1));
                uint32_t aoff = arow * 128 + ((c8a ^ ulr) << 4);
                uint32_t qhh[4], qll[4];
                ldsm_x4(qhh[0], qhh[1], qhh[2], qhh[3], uQhb + aoff);
                ldsm_x4(qll[0], qll[1], qll[2], qll[3], uQlb + aoff);
                uint32_t c8b = (uint32_t)(s * 2 + (g8 & 1));
                uint32_t bcol = (c8b ^ ulr) << 4;
#pragma unroll
                for (int np = 0; np < 8; np++) {
                    uint32_t brow = (uint32_t)(np * 16 + lr + ((g8 >> 1) << 3));
                    uint32_t kf[4];
                    ldsm_x4(kf[0], kf[1], kf[2], kf[3], uKb + brow * 128 + bcol);
                    mma_f16(acc[2 * np],     qhh, kf[0], kf[1]);
                    mma_f16(acc[2 * np + 1], qhh, kf[2], kf[3]);
                    mma_f16(acc[2 * np],     qll, kf[0], kf[1]);
                    mma_f16(acc[2 * np + 1], qll, kf[2], kf[3]);
                }
            }
        }

        // ---- Online softmax ----
        float mx0 = -1e30f, mx1 = -1e30f;
#pragma unroll
        for (int nt = 0; nt < 16; nt++) {
            mx0 = fmaxf(mx0, fmaxf(acc[nt][0], acc[nt][1]));
            mx1 = fmaxf(mx1, fmaxf(acc[nt][2], acc[nt][3]));
        }
        mx0 = fmaxf(mx0, __shfl_xor_sync(0xFFFFFFFFu, mx0, 1));
        mx0 = fmaxf(mx0, __shfl_xor_sync(0xFFFFFFFFu, mx0, 2));
        mx1 = fmaxf(mx1, __shfl_xor_sync(0xFFFFFFFFu, mx1, 1));
        mx1 = fmaxf(mx1, __shfl_xor_sync(0xFFFFFFFFu, mx1, 2));
        float mn0 = fmaxf(m0, mx0), mn1 = fmaxf(m1, mx1);
        float corr0 = exp2p((m0 - mn0) * LOG2E);
        float corr1 = exp2p((m1 - mn1) * LOG2E);
        m0 = mn0; m1 = mn1;

        float sum0 = 0.0f, sum1 = 0.0f;
#pragma unroll
        for (int nt = 0; nt < 16; nt++) {
            acc[nt][0] = exp2p((acc[nt][0] - mn0) * LOG2E);
            acc[nt][1] = exp2p((acc[nt][1] - mn0) * LOG2E);
            acc[nt][2] = exp2p((acc[nt][2] - mn1) * LOG2E);
            acc[nt][3] = exp2p((acc[nt][3] - mn1) * LOG2E);
            sum0 += acc[nt][0] + acc[nt][1];
            sum1 += acc[nt][2] + acc[nt][3];
        }
        sum0 += __shfl_xor_sync(0xFFFFFFFFu, sum0, 1);
        sum0 += __shfl_xor_sync(0xFFFFFFFFu, sum0, 2);
        sum1 += __shfl_xor_sync(0xFFFFFFFFu, sum1, 1);
        sum1 += __shfl_xor_sync(0xFFFFFFFFu, sum1, 2);
        l0 = l0 * corr0 + sum0;
        l1 = l1 * corr1 + sum1;

#pragma unroll
        for (int nd = 0; nd < 16; nd++) {
            accO[nd][0] *= corr0; accO[nd][1] *= corr0;
            accO[nd][2] *= corr1; accO[nd][3] *= corr1;
        }

        // ---- O += P V ----
#pragma unroll
        for (int kk = 0; kk < 8; kk++) {
            uint32_t pah[4], pal[4];
            {
                int n0 = 2 * kk, n1 = 2 * kk + 1;
                split2h(acc[n0][0], acc[n0][1], pah[0], pal[0]);
                split2h(acc[n0][2], acc[n0][3], pah[1], pal[1]);
                split2h(acc[n1][0], acc[n1][1], pah[2], pal[2]);
                split2h(acc[n1][2], acc[n1][3], pah[3], pal[3]);
            }
            uint32_t vrow = (uint32_t)(kk * 16 + lr + ((g8 & 1) << 3));
#pragma unroll
            for (int half = 0; half < 2; half++) {
                uint32_t vf[4][4];
#pragma unroll
                for (int j = 0; j < 4; j++) {
                    uint32_t ndp = (uint32_t)(half * 4 + j);
                    uint32_t blkv = ndp >> 2;
                    uint32_t c8v = (ndp & 3) * 2 + (uint32_t)(g8 >> 1);
                    uint32_t voff = blkv * TB + vrow * 128 + ((c8v ^ ulr) << 4);
                    ldsm_x4_t(vf[j][0], vf[j][1], vf[j][2], vf[j][3], uV + voff);
                }
#pragma unroll
                for (int j = 0; j < 4; j++) {
                    int nda = (half * 4 + j) * 2, ndb = nda + 1;
                    mma_f16(accO[nda], pah, vf[j][0], vf[j][1]);
                    mma_f16(accO[ndb], pah, vf[j][2], vf[j][3]);
                    mma_f16(accO[nda], pal, vf[j][0], vf[j][1]);
                    mma_f16(accO[ndb], pal, vf[j][2], vf[j][3]);
                }
            }
        }

        __syncthreads();
        if (kt + 2 < 16 && tid == 0) {
            FENCE_PROXY_ASYNC();
            issueKV(st, kt + 2);
        }
    }

    // ---- Epilogue: normalize, split fp16, write TILED hi/lo layout ----
    float inv0 = 1.0f / l0, inv1 = 1.0f / l1;
    const int mrow0 = b * N_SZ + qt * 128 + warp * 16 + g4;   // row1 = +8
    const int panel = mrow0 >> 7;
    const int r0 = mrow0 & 127;
    const uint32_t rsw = (uint32_t)(r0 & 7);
#pragma unroll
    for (int nd = 0; nd < 16; nd++) {
        int kchunk = h * 2 + (nd >> 3);
        uint32_t c8 = (uint32_t)(nd & 7);
        size_t blk = (size_t)(panel * 32 + kchunk) * TB;
        uint32_t in0 = (uint32_t)(r0 * 128) + ((c8 ^ rsw) << 4) + t4 * 4;
        uint32_t hw, lw;
        split2h(accO[nd][0] * inv0, accO[nd][1] * inv0, hw, lw);
        *(uint32_t*)((char*)oh + blk + in0) = hw;
        *(uint32_t*)((char*)ol + blk + in0) = lw;
        split2h(accO[nd][2] * inv1, accO[nd][3] * inv1, hw, lw);
        *(uint32_t*)((char*)oh + blk + in0 + 1024) = hw;
        *(uint32_t*)((char*)ol + blk + in0 + 1024) = lw;
    }
}

// ---------------------------------------------------------------------------
// Launch
// ---------------------------------------------------------------------------
extern "C" void kernel_launch(void* const* d_in, const int* in_sizes, int n_in,
                              void* d_out, int out_size) {
    const float* x  = (const float*)d_in[0];
    const float* Wq = (const float*)d_in[1];
    const float* Wk = (const float*)d_in[2];
    const float* Wv = (const float*)d_in[3];
    const float* Wo = (const float*)d_in[4];
    float* out = (float*)d_out;

    float *q_ptr, *k_ptr, *v_ptr;
    __half *xh, *xl, *wh, *oh, *ol, *qhp, *qlp, *khp, *vhp;
    cudaGetSymbolAddress((void**)&q_ptr, g_q);
    cudaGetSymbolAddress((void**)&k_ptr, g_k);
    cudaGetSymbolAddress((void**)&v_ptr, g_v);
    cudaGetSymbolAddress((void**)&xh, g_xh);
    cudaGetSymbolAddress((void**)&xl, g_xl);
    cudaGetSymbolAddress((void**)&wh, g_wh);
    cudaGetSymbolAddress((void**)&oh, g_oh);
    cudaGetSymbolAddress((void**)&ol, g_ol);
    cudaGetSymbolAddress((void**)&qhp, g_qh);
    cudaGetSymbolAddress((void**)&qlp, g_ql);
    cudaGetSymbolAddress((void**)&khp, g_kh);
    cudaGetSymbolAddress((void**)&vhp, g_vh);

    cudaFuncSetAttribute(gemm7, cudaFuncAttributeMaxDynamicSharedMemorySize,
                         G7_SMEM);
    cudaFuncSetAttribute(attn2, cudaFuncAttributeMaxDynamicSharedMemorySize,
                         ATT2_SMEM);

    const size_t woff = (size_t)D_SZ * D_SZ;

    // Pre-split + tile operands (weights: hi only)
    split_tiled<<<M_SZ, 256>>>(x, xh, xl, M_SZ);
    split_tiled_h<<<D_SZ, 256>>>(Wq, wh, D_SZ);
    split_tiled_h<<<D_SZ, 256>>>(Wk, wh + woff, D_SZ);
    split_tiled_h<<<D_SZ, 256>>>(Wv, wh + 2 * woff, D_SZ);
    split_tiled_h<<<D_SZ, 256>>>(Wo, wh + 3 * woff, D_SZ);

    // Fused Q/K/V projection
    dim3 gq(D_SZ / 128, M_SZ / 128, 3);    // (16, 32, 3)
    gemm7<<<gq, 256, G7_SMEM>>>(xh, xl, wh, q_ptr, k_ptr, v_ptr, D_SZ);

    // RoPE + convert to tiled fp16 (Q hi+lo scaled, K hi, V hi)
    rope_convert<<<(M_SZ * H_SZ * 8) / 256, 256>>>(q_ptr, k_ptr, v_ptr,
                                                   qhp, qlp, khp, vhp);

    dim3 ga(N_SZ / 128, B_SZ * H_SZ);      // (16, 32)
    attn2<<<ga, 256, ATT2_SMEM>>>(qhp, qlp, khp, vhp, oh, ol);

    // O projection
    dim3 go(D_SZ / 128, M_SZ / 128, 1);
    gemm7<<<go, 256, G7_SMEM>>>(oh, ol, wh + 3 * woff, out, out, out, D_SZ);
}